// round 10
// baseline (speedup 1.0000x reference)
#include <cuda_runtime.h>
#include <cuda.h>
#include <cuda_fp16.h>
#include <cstdint>

// ---------------------------------------------------------------------------
// Problem constants
// ---------------------------------------------------------------------------
#define D_IN   4096
#define D_OUT  4096
#define M_TOT  8192
#define RANK   64

// GEMM tiling (fp16 operands, fp32 accumulate)
#define TM 128
#define TN 128
#define TK 64                        // halves per K-stage = 128 B (one SW128 row)
#define STAGES 3
#define K_ITERS (D_IN / TK)          // 64
#define M_TILES (M_TOT / TM)         // 64
#define N_TILES (D_OUT / TN)         // 32

#define A_STAGE_B (TM * 128)         // 16384 bytes
#define B_STAGE_B (TN * 128)         // 16384 bytes
#define SMEM_FULL(s)  ((s) * 8)
#define SMEM_A_OFF    1024
#define SMEM_B_OFF    (SMEM_A_OFF + STAGES * A_STAGE_B)     // 50176
#define SMEM_BYTES    (SMEM_B_OFF + STAGES * B_STAGE_B)     // 99328 -> 2 CTAs/SM

// prep kernel partition
#define CONV_BLOCKS 2048
#define WEFF_BLOCKS ((D_IN / 64) * (D_OUT / 64))   // 4096

// ---------------------------------------------------------------------------
// Device globals (allocation-free scratch)
// ---------------------------------------------------------------------------
__constant__ float c_nf4[16] = {
    -1.0f, -0.6962f, -0.5251f, -0.3949f, -0.2844f, -0.1848f,
    -0.0911f, 0.0f, 0.0796f, 0.1609f, 0.2461f, 0.3379f,
    0.4407f, 0.5626f, 0.723f, 1.0f};

__device__ __align__(1024) __half g_wh[(size_t)D_OUT * D_IN];
__device__ __align__(1024) __half g_xh[(size_t)M_TOT * D_IN];

// ---------------------------------------------------------------------------
// PTX helpers
// ---------------------------------------------------------------------------
#define LDMATRIX_X4(r0, r1, r2, r3, addr)                                     \
    asm volatile("ldmatrix.sync.aligned.m8n8.x4.shared.b16 {%0,%1,%2,%3}, [%4];" \
                 : "=r"(r0), "=r"(r1), "=r"(r2), "=r"(r3) : "r"(addr))

__device__ __forceinline__ void mma_f16(float* c, const uint32_t* a,
                                        uint32_t b0, uint32_t b1) {
    asm volatile(
        "mma.sync.aligned.m16n8k16.row.col.f32.f16.f16.f32 "
        "{%0,%1,%2,%3}, {%4,%5,%6,%7}, {%8,%9}, {%0,%1,%2,%3};"
        : "+f"(c[0]), "+f"(c[1]), "+f"(c[2]), "+f"(c[3])
        : "r"(a[0]), "r"(a[1]), "r"(a[2]), "r"(a[3]), "r"(b0), "r"(b1));
}

#define MBAR_INIT(addr, cnt) \
    asm volatile("mbarrier.init.shared.b64 [%0], %1;" :: "r"(addr), "r"(cnt) : "memory")

#define MBAR_EXPECT_TX(addr, bytes) \
    asm volatile("mbarrier.arrive.expect_tx.shared.b64 _, [%0], %1;" \
                 :: "r"(addr), "r"(bytes) : "memory")

#define MBAR_WAIT(addr, ph) do {                                                  \
    uint32_t _d = 0;                                                              \
    do {                                                                          \
        asm volatile("{\n\t.reg .pred P;\n\t"                                     \
            "mbarrier.try_wait.parity.acquire.cta.shared::cta.b64 P, [%1], %2, 0x989680;\n\t" \
            "selp.b32 %0, 1, 0, P;\n\t}"                                          \
            : "=r"(_d) : "r"(addr), "r"(ph) : "memory");                          \
    } while (!_d);                                                                \
} while (0)

#define TMA_LOAD_2D(smem_addr, tmap, cx, cy, mbar) \
    asm volatile( \
        "cp.async.bulk.tensor.2d.shared::cta.global.tile.mbarrier::complete_tx::bytes " \
        "[%0], [%1, {%2, %3}], [%4];" \
        :: "r"(smem_addr), "l"(tmap), "r"(cx), "r"(cy), "r"(mbar) : "memory")

__device__ __forceinline__ uint32_t h2_bits(__half2 h) {
    return *reinterpret_cast<uint32_t*>(&h);
}

// ---------------------------------------------------------------------------
// Fused prep: blocks [0, CONV_BLOCKS) convert x -> fp16;
//             blocks [CONV_BLOCKS, ...) build W_eff -> fp16.
// Disjoint outputs, no cross-block dependency.
// ---------------------------------------------------------------------------
__global__ __launch_bounds__(256) void prep_kernel(
    const float4* __restrict__ x, uint2* __restrict__ xh, int n4,
    const int* __restrict__ q, const float* __restrict__ wscale,
    const float* __restrict__ lA, const float* __restrict__ lB,
    uint2* __restrict__ wh) {
    const int tid = threadIdx.x;

    if (blockIdx.x < CONV_BLOCKS) {
        int i = blockIdx.x * blockDim.x + tid;
        const int stride = CONV_BLOCKS * blockDim.x;
        for (; i < n4; i += stride) {
            float4 v = x[i];
            uint2 o;
            o.x = h2_bits(__floats2half2_rn(v.x, v.y));
            o.y = h2_bits(__floats2half2_rn(v.z, v.w));
            xh[i] = o;
        }
        return;
    }

    __shared__ float sA[64][68];
    __shared__ float sB[64][68];
    const int wb = blockIdx.x - CONV_BLOCKS;
    const int i0 = (wb & 63) * 64;      // D_IN/64 = 64 tiles
    const int o0 = (wb >> 6) * 64;

    for (int idx = tid; idx < 64 * 64; idx += 256) {
        int r = idx >> 6, c = idx & 63;
        sA[r][c] = lA[r * D_IN + i0 + c];
    }
    for (int idx = tid; idx < 64 * 64; idx += 256) {
        int o = idx >> 6, r = idx & 63;
        sB[r][o] = lB[(size_t)(o0 + o) * RANK + r];
    }
    __syncthreads();

    const int tx = tid & 15;
    const int ty = tid >> 4;
    float acc[4][4] = {};
#pragma unroll
    for (int r = 0; r < 64; r++) {
        const float4 av = *reinterpret_cast<const float4*>(&sA[r][tx * 4]);
        const float4 bv = *reinterpret_cast<const float4*>(&sB[r][ty * 4]);
        const float a[4] = {av.x, av.y, av.z, av.w};
        const float b[4] = {bv.x, bv.y, bv.z, bv.w};
#pragma unroll
        for (int ii = 0; ii < 4; ii++)
#pragma unroll
            for (int jj = 0; jj < 4; jj++)
                acc[ii][jj] += b[ii] * a[jj];
    }

    const float s = wscale[0];
#pragma unroll
    for (int ii = 0; ii < 4; ii++) {
        const size_t o = o0 + ty * 4 + ii;
        const int4 qv = *reinterpret_cast<const int4*>(&q[o * D_IN + i0 + tx * 4]);
        float f0 = c_nf4[qv.x & 15] * s + 0.25f * acc[ii][0];
        float f1 = c_nf4[qv.y & 15] * s + 0.25f * acc[ii][1];
        float f2 = c_nf4[qv.z & 15] * s + 0.25f * acc[ii][2];
        float f3 = c_nf4[qv.w & 15] * s + 0.25f * acc[ii][3];
        uint2 o2;
        o2.x = h2_bits(__floats2half2_rn(f0, f1));
        o2.y = h2_bits(__floats2half2_rn(f2, f3));
        wh[(o * D_IN + i0 + tx * 4) >> 2] = o2;
    }
}

// ---------------------------------------------------------------------------
// Main GEMM: C[m,n] = sum_k Xh[m,k] * Wh[n,k]
// 128x128 CTA, 4 warps (64x64 tiles), TMA + full-mbarriers, stage release via
// __syncthreads (R8-proven discipline); 2 CTAs/SM.
// ---------------------------------------------------------------------------
__global__ void __launch_bounds__(128, 2)
gemm_f16_kernel(const __grid_constant__ CUtensorMap tma_a,
                const __grid_constant__ CUtensorMap tma_b,
                float* __restrict__ C) {
    extern __shared__ char smem[];
    const uint32_t sb = (uint32_t)__cvta_generic_to_shared(smem);

    const int tid = threadIdx.x;
    const int warp = tid >> 5;
    const int lane = tid & 31;

    const int bid = blockIdx.x;
    const int GROUP_M = 8;
    const int per_group = GROUP_M * N_TILES;
    const int g = bid / per_group, rem = bid % per_group;
    const int mt = g * GROUP_M + (rem % GROUP_M);
    const int nt = rem / GROUP_M;
    const int m0 = mt * TM, n0 = nt * TN;

    const int wm = (warp & 1) * 64;
    const int wn = (warp >> 1) * 64;

    if (tid == 0) {
        for (int s = 0; s < STAGES; s++)
            MBAR_INIT(sb + SMEM_FULL(s), 1);
        asm volatile("fence.proxy.async.shared::cta;" ::: "memory");
    }
    __syncthreads();

    // prologue: load all STAGES stages
    if (tid == 0) {
#pragma unroll
        for (int s = 0; s < STAGES; s++) {
            MBAR_EXPECT_TX(sb + SMEM_FULL(s), A_STAGE_B + B_STAGE_B);
            TMA_LOAD_2D(sb + SMEM_A_OFF + s * A_STAGE_B, &tma_a, s * TK, m0,
                        sb + SMEM_FULL(s));
            TMA_LOAD_2D(sb + SMEM_B_OFF + s * B_STAGE_B, &tma_b, s * TK, n0,
                        sb + SMEM_FULL(s));
        }
    }

    float acc[4][8][4];
#pragma unroll
    for (int mi = 0; mi < 4; mi++)
#pragma unroll
        for (int ni = 0; ni < 8; ni++)
#pragma unroll
            for (int c = 0; c < 4; c++) acc[mi][ni][c] = 0.f;

    // ldmatrix lane addressing (SW128 swizzle: 16B chunk ^= row & 7)
    const int lg = lane >> 3;
    const int lr = lane & 7;
    const int a_row = lr + (lg & 1) * 8;
    const int a_kch = lg >> 1;
    const int b_row = lr + (lg >> 1) * 8;
    const int b_kch = lg & 1;

    uint32_t af[2][4][4];
    uint32_t bf[2][4][4];

    auto load_frag = [&](int buf, uint32_t a_st, uint32_t b_st, int kk) {
#pragma unroll
        for (int mi = 0; mi < 4; mi++) {
            const int row = wm + mi * 16 + a_row;
            const int ch = (2 * kk + a_kch) ^ (row & 7);
            uint32_t addr = a_st + row * 128 + ch * 16;
            LDMATRIX_X4(af[buf][mi][0], af[buf][mi][1], af[buf][mi][2], af[buf][mi][3], addr);
        }
#pragma unroll
        for (int nj = 0; nj < 4; nj++) {
            const int row = wn + nj * 16 + b_row;
            const int ch = (2 * kk + b_kch) ^ (row & 7);
            uint32_t addr = b_st + row * 128 + ch * 16;
            LDMATRIX_X4(bf[buf][nj][0], bf[buf][nj][1], bf[buf][nj][2], bf[buf][nj][3], addr);
        }
    };

    int cs = 0, cph = 0;

    for (int kt = 0; kt < K_ITERS; kt++) {
        // wait for stage kt's data
        MBAR_WAIT(sb + SMEM_FULL(cs), cph);

        const uint32_t a_st = sb + SMEM_A_OFF + cs * A_STAGE_B;
        const uint32_t b_st = sb + SMEM_B_OFF + cs * B_STAGE_B;

        load_frag(0, a_st, b_st, 0);
#pragma unroll
        for (int kk = 0; kk < 4; kk++) {
            const int cur = kk & 1;
            if (kk < 3)
                load_frag(cur ^ 1, a_st, b_st, kk + 1);
#pragma unroll
            for (int mi = 0; mi < 4; mi++)
#pragma unroll
                for (int nj = 0; nj < 4; nj++) {
                    mma_f16(acc[mi][nj * 2 + 0], af[cur][mi], bf[cur][nj][0], bf[cur][nj][1]);
                    mma_f16(acc[mi][nj * 2 + 1], af[cur][mi], bf[cur][nj][2], bf[cur][nj][3]);
                }
        }

        // stage release: everyone done reading slot cs
        __syncthreads();

        // refill slot cs with k-iter kt+STAGES
        if (tid == 0 && kt + STAGES < K_ITERS) {
            const int li = kt + STAGES;
            MBAR_EXPECT_TX(sb + SMEM_FULL(cs), A_STAGE_B + B_STAGE_B);
            TMA_LOAD_2D(sb + SMEM_A_OFF + cs * A_STAGE_B, &tma_a, li * TK, m0,
                        sb + SMEM_FULL(cs));
            TMA_LOAD_2D(sb + SMEM_B_OFF + cs * B_STAGE_B, &tma_b, li * TK, n0,
                        sb + SMEM_FULL(cs));
        }

        if (++cs == STAGES) { cs = 0; cph ^= 1; }
    }

    // epilogue
    const int crow = lane >> 2;
    const int ccol = (lane & 3) * 2;
#pragma unroll
    for (int mi = 0; mi < 4; mi++) {
#pragma unroll
        for (int ni = 0; ni < 8; ni++) {
            const size_t m = (size_t)m0 + wm + mi * 16 + crow;
            const int n = n0 + wn + ni * 8 + ccol;
            float2 v0 = {acc[mi][ni][0], acc[mi][ni][1]};
            float2 v1 = {acc[mi][ni][2], acc[mi][ni][3]};
            *reinterpret_cast<float2*>(C + m * D_OUT + n) = v0;
            *reinterpret_cast<float2*>(C + (m + 8) * D_OUT + n) = v1;
        }
    }
}

// ---------------------------------------------------------------------------
// Host side
// ---------------------------------------------------------------------------
typedef CUresult (*EncodeFn)(CUtensorMap*, CUtensorMapDataType, cuuint32_t, void*,
                             const cuuint64_t*, const cuuint64_t*, const cuuint32_t*,
                             const cuuint32_t*, CUtensorMapInterleave, CUtensorMapSwizzle,
                             CUtensorMapL2promotion, CUtensorMapFloatOOBfill);

static EncodeFn get_encode_fn() {
    void* fn = nullptr;
    cudaDriverEntryPointQueryResult st;
#if CUDART_VERSION >= 12050
    cudaGetDriverEntryPointByVersion("cuTensorMapEncodeTiled", &fn, 12000,
                                     cudaEnableDefault, &st);
#else
    cudaGetDriverEntryPoint("cuTensorMapEncodeTiled", &fn, cudaEnableDefault, &st);
#endif
    return (EncodeFn)fn;
}

static void encode_2d_f16(EncodeFn fn, CUtensorMap* tm, void* ptr,
                          uint64_t dim0, uint64_t dim1, uint32_t box0, uint32_t box1) {
    cuuint64_t dims[2] = {dim0, dim1};
    cuuint64_t strides[1] = {dim0 * 2};
    cuuint32_t box[2] = {box0, box1};
    cuuint32_t es[2] = {1, 1};
    fn(tm, CU_TENSOR_MAP_DATA_TYPE_FLOAT16, 2, ptr, dims, strides, box, es,
       CU_TENSOR_MAP_INTERLEAVE_NONE, CU_TENSOR_MAP_SWIZZLE_128B,
       CU_TENSOR_MAP_L2_PROMOTION_L2_128B, CU_TENSOR_MAP_FLOAT_OOB_FILL_NONE);
}

extern "C" void kernel_launch(void* const* d_in, const int* in_sizes, int n_in,
                              void* d_out, int out_size) {
    const float* x  = (const float*)d_in[0];
    const int*   q  = (const int*)d_in[1];
    const float* ws = (const float*)d_in[2];
    const float* lA = (const float*)d_in[3];
    const float* lB = (const float*)d_in[4];
    float* out = (float*)d_out;

    __half* wh = nullptr;
    __half* xh = nullptr;
    cudaGetSymbolAddress((void**)&wh, g_wh);
    cudaGetSymbolAddress((void**)&xh, g_xh);

    prep_kernel<<<CONV_BLOCKS + WEFF_BLOCKS, 256>>>(
        (const float4*)x, (uint2*)xh, (int)((size_t)M_TOT * D_IN / 4),
        q, ws, lA, lB, (uint2*)wh);

    EncodeFn enc = get_encode_fn();
    CUtensorMap tm_a, tm_b;
    encode_2d_f16(enc, &tm_a, xh, D_IN, M_TOT, TK, TM);
    encode_2d_f16(enc, &tm_b, wh, D_IN, D_OUT, TK, TN);

    cudaFuncSetAttribute(gemm_f16_kernel,
                         cudaFuncAttributeMaxDynamicSharedMemorySize, SMEM_BYTES);
    gemm_f16_kernel<<<M_TILES * N_TILES, 128, SMEM_BYTES>>>(tm_a, tm_b, out);
}

// round 11
// speedup vs baseline: 1.0684x; 1.0684x over previous
#include <cuda_runtime.h>
#include <cuda.h>
#include <cuda_fp16.h>
#include <cstdint>

// ---------------------------------------------------------------------------
// Problem constants
// ---------------------------------------------------------------------------
#define D_IN   4096
#define D_OUT  4096
#define M_TOT  8192
#define RANK   64

// GEMM tiling (fp16 operands, fp32 accumulate)
#define TM 128
#define TN 128
#define TK 64                        // halves per K-stage = 128 B (one SW128 row)
#define STAGES 3
#define K_ITERS (D_IN / TK)          // 64
#define M_TILES (M_TOT / TM)         // 64
#define N_TILES (D_OUT / TN)         // 32

#define A_STAGE_B (TM * 128)         // 16384 bytes
#define B_STAGE_B (TN * 128)         // 16384 bytes
#define SMEM_FULL(s)  ((s) * 8)
#define SMEM_A_OFF    1024
#define SMEM_B_OFF    (SMEM_A_OFF + STAGES * A_STAGE_B)     // 50176
#define SMEM_BYTES    (SMEM_B_OFF + STAGES * B_STAGE_B)     // 99328 -> 2 CTAs/SM

// ---------------------------------------------------------------------------
// Device globals (allocation-free scratch)
// ---------------------------------------------------------------------------
__constant__ float c_nf4[16] = {
    -1.0f, -0.6962f, -0.5251f, -0.3949f, -0.2844f, -0.1848f,
    -0.0911f, 0.0f, 0.0796f, 0.1609f, 0.2461f, 0.3379f,
    0.4407f, 0.5626f, 0.723f, 1.0f};

__device__ __align__(1024) __half g_wh[(size_t)D_OUT * D_IN];
__device__ __align__(1024) __half g_xh[(size_t)M_TOT * D_IN];

// ---------------------------------------------------------------------------
// PTX helpers
// ---------------------------------------------------------------------------
#define LDMATRIX_X4(r0, r1, r2, r3, addr)                                     \
    asm volatile("ldmatrix.sync.aligned.m8n8.x4.shared.b16 {%0,%1,%2,%3}, [%4];" \
                 : "=r"(r0), "=r"(r1), "=r"(r2), "=r"(r3) : "r"(addr))

__device__ __forceinline__ void mma_f16(float* c, const uint32_t* a,
                                        uint32_t b0, uint32_t b1) {
    asm volatile(
        "mma.sync.aligned.m16n8k16.row.col.f32.f16.f16.f32 "
        "{%0,%1,%2,%3}, {%4,%5,%6,%7}, {%8,%9}, {%0,%1,%2,%3};"
        : "+f"(c[0]), "+f"(c[1]), "+f"(c[2]), "+f"(c[3])
        : "r"(a[0]), "r"(a[1]), "r"(a[2]), "r"(a[3]), "r"(b0), "r"(b1));
}

#define MBAR_INIT(addr, cnt) \
    asm volatile("mbarrier.init.shared.b64 [%0], %1;" :: "r"(addr), "r"(cnt) : "memory")

#define MBAR_EXPECT_TX(addr, bytes) \
    asm volatile("mbarrier.arrive.expect_tx.shared.b64 _, [%0], %1;" \
                 :: "r"(addr), "r"(bytes) : "memory")

#define MBAR_WAIT(addr, ph) do {                                                  \
    uint32_t _d = 0;                                                              \
    do {                                                                          \
        asm volatile("{\n\t.reg .pred P;\n\t"                                     \
            "mbarrier.try_wait.parity.acquire.cta.shared::cta.b64 P, [%1], %2, 0x989680;\n\t" \
            "selp.b32 %0, 1, 0, P;\n\t}"                                          \
            : "=r"(_d) : "r"(addr), "r"(ph) : "memory");                          \
    } while (!_d);                                                                \
} while (0)

#define TMA_LOAD_2D(smem_addr, tmap, cx, cy, mbar) \
    asm volatile( \
        "cp.async.bulk.tensor.2d.shared::cta.global.tile.mbarrier::complete_tx::bytes " \
        "[%0], [%1, {%2, %3}], [%4];" \
        :: "r"(smem_addr), "l"(tmap), "r"(cx), "r"(cy), "r"(mbar) : "memory")

__device__ __forceinline__ uint32_t h2_bits(__half2 h) {
    return *reinterpret_cast<uint32_t*>(&h);
}

// ---------------------------------------------------------------------------
// Prep 1: convert x to fp16 (separate launch — no smem, full occupancy)
// ---------------------------------------------------------------------------
__global__ __launch_bounds__(256) void convert_x_kernel(const float4* __restrict__ x,
                                                        uint2* __restrict__ xh, int n4) {
    int i = blockIdx.x * blockDim.x + threadIdx.x;
    int stride = gridDim.x * blockDim.x;
    for (; i < n4; i += stride) {
        float4 v = x[i];
        uint2 o;
        o.x = h2_bits(__floats2half2_rn(v.x, v.y));
        o.y = h2_bits(__floats2half2_rn(v.z, v.w));
        xh[i] = o;
    }
}

// ---------------------------------------------------------------------------
// Prep 2: W_eff[o,i] = NF4[q[o,i]]*scale + 0.25 * (B@A)[o,i], to fp16
// ---------------------------------------------------------------------------
__global__ __launch_bounds__(256) void prep_weff_kernel(
    const int* __restrict__ q, const float* __restrict__ wscale,
    const float* __restrict__ lA, const float* __restrict__ lB,
    uint2* __restrict__ wh) {
    __shared__ float sA[64][68];
    __shared__ float sB[64][68];
    const int tid = threadIdx.x;
    const int i0 = blockIdx.x * 64;
    const int o0 = blockIdx.y * 64;

    for (int idx = tid; idx < 64 * 64; idx += 256) {
        int r = idx >> 6, c = idx & 63;
        sA[r][c] = lA[r * D_IN + i0 + c];
    }
    for (int idx = tid; idx < 64 * 64; idx += 256) {
        int o = idx >> 6, r = idx & 63;
        sB[r][o] = lB[(size_t)(o0 + o) * RANK + r];
    }
    __syncthreads();

    const int tx = tid & 15;
    const int ty = tid >> 4;
    float acc[4][4] = {};
#pragma unroll
    for (int r = 0; r < 64; r++) {
        const float4 av = *reinterpret_cast<const float4*>(&sA[r][tx * 4]);
        const float4 bv = *reinterpret_cast<const float4*>(&sB[r][ty * 4]);
        const float a[4] = {av.x, av.y, av.z, av.w};
        const float b[4] = {bv.x, bv.y, bv.z, bv.w};
#pragma unroll
        for (int ii = 0; ii < 4; ii++)
#pragma unroll
            for (int jj = 0; jj < 4; jj++)
                acc[ii][jj] += b[ii] * a[jj];
    }

    const float s = wscale[0];
#pragma unroll
    for (int ii = 0; ii < 4; ii++) {
        const size_t o = o0 + ty * 4 + ii;
        const int4 qv = *reinterpret_cast<const int4*>(&q[o * D_IN + i0 + tx * 4]);
        float f0 = c_nf4[qv.x & 15] * s + 0.25f * acc[ii][0];
        float f1 = c_nf4[qv.y & 15] * s + 0.25f * acc[ii][1];
        float f2 = c_nf4[qv.z & 15] * s + 0.25f * acc[ii][2];
        float f3 = c_nf4[qv.w & 15] * s + 0.25f * acc[ii][3];
        uint2 o2;
        o2.x = h2_bits(__floats2half2_rn(f0, f1));
        o2.y = h2_bits(__floats2half2_rn(f2, f3));
        wh[(o * D_IN + i0 + tx * 4) >> 2] = o2;
    }
}

// ---------------------------------------------------------------------------
// Main GEMM: C[m,n] = sum_k Xh[m,k] * Wh[n,k]
// 128x128 CTA, 4 warps (64x64 tiles), TMA + full-mbarriers; next-stage wait +
// fragment prefetch overlapped with last MMA burst; release via __syncthreads.
// ---------------------------------------------------------------------------
__global__ void __launch_bounds__(128, 2)
gemm_f16_kernel(const __grid_constant__ CUtensorMap tma_a,
                const __grid_constant__ CUtensorMap tma_b,
                float* __restrict__ C) {
    extern __shared__ char smem[];
    const uint32_t sb = (uint32_t)__cvta_generic_to_shared(smem);

    const int tid = threadIdx.x;
    const int warp = tid >> 5;
    const int lane = tid & 31;

    const int bid = blockIdx.x;
    const int GROUP_M = 8;
    const int per_group = GROUP_M * N_TILES;
    const int g = bid / per_group, rem = bid % per_group;
    const int mt = g * GROUP_M + (rem % GROUP_M);
    const int nt = rem / GROUP_M;
    const int m0 = mt * TM, n0 = nt * TN;

    const int wm = (warp & 1) * 64;
    const int wn = (warp >> 1) * 64;

    if (tid == 0) {
        for (int s = 0; s < STAGES; s++)
            MBAR_INIT(sb + SMEM_FULL(s), 1);
        asm volatile("fence.proxy.async.shared::cta;" ::: "memory");
    }
    __syncthreads();

    // prologue: load all STAGES stages
    if (tid == 0) {
#pragma unroll
        for (int s = 0; s < STAGES; s++) {
            MBAR_EXPECT_TX(sb + SMEM_FULL(s), A_STAGE_B + B_STAGE_B);
            TMA_LOAD_2D(sb + SMEM_A_OFF + s * A_STAGE_B, &tma_a, s * TK, m0,
                        sb + SMEM_FULL(s));
            TMA_LOAD_2D(sb + SMEM_B_OFF + s * B_STAGE_B, &tma_b, s * TK, n0,
                        sb + SMEM_FULL(s));
        }
    }

    float acc[4][8][4];
#pragma unroll
    for (int mi = 0; mi < 4; mi++)
#pragma unroll
        for (int ni = 0; ni < 8; ni++)
#pragma unroll
            for (int c = 0; c < 4; c++) acc[mi][ni][c] = 0.f;

    // ldmatrix lane addressing (SW128 swizzle: 16B chunk ^= row & 7)
    const int lg = lane >> 3;
    const int lr = lane & 7;
    const int a_row = lr + (lg & 1) * 8;
    const int a_kch = lg >> 1;
    const int b_row = lr + (lg >> 1) * 8;
    const int b_kch = lg & 1;

    uint32_t af[2][4][4];
    uint32_t bf[2][4][4];

    auto load_frag = [&](int buf, uint32_t a_st, uint32_t b_st, int kk) {
#pragma unroll
        for (int mi = 0; mi < 4; mi++) {
            const int row = wm + mi * 16 + a_row;
            const int ch = (2 * kk + a_kch) ^ (row & 7);
            uint32_t addr = a_st + row * 128 + ch * 16;
            LDMATRIX_X4(af[buf][mi][0], af[buf][mi][1], af[buf][mi][2], af[buf][mi][3], addr);
        }
#pragma unroll
        for (int nj = 0; nj < 4; nj++) {
            const int row = wn + nj * 16 + b_row;
            const int ch = (2 * kk + b_kch) ^ (row & 7);
            uint32_t addr = b_st + row * 128 + ch * 16;
            LDMATRIX_X4(bf[buf][nj][0], bf[buf][nj][1], bf[buf][nj][2], bf[buf][nj][3], addr);
        }
    };

    int cs = 0, cph = 0;

    // prime: wait stage 0, load its kk=0 fragments into buf 0
    MBAR_WAIT(sb + SMEM_FULL(0), 0);
    load_frag(0, sb + SMEM_A_OFF, sb + SMEM_B_OFF, 0);

    for (int kt = 0; kt < K_ITERS; kt++) {
        const uint32_t a_st = sb + SMEM_A_OFF + cs * A_STAGE_B;
        const uint32_t b_st = sb + SMEM_B_OFF + cs * B_STAGE_B;

        // next-stage cursor
        const int ncs = (cs + 1 == STAGES) ? 0 : cs + 1;
        const int nph = (cs + 1 == STAGES) ? (cph ^ 1) : cph;

#pragma unroll
        for (int kk = 0; kk < 4; kk++) {
            const int cur = kk & 1;
            if (kk < 3) {
                load_frag(cur ^ 1, a_st, b_st, kk + 1);
            } else if (kt + 1 < K_ITERS) {
                // overlap next stage's wait + kk=0 frag load with this MMA burst
                MBAR_WAIT(sb + SMEM_FULL(ncs), nph);
                load_frag(cur ^ 1, sb + SMEM_A_OFF + ncs * A_STAGE_B,
                          sb + SMEM_B_OFF + ncs * B_STAGE_B, 0);
            }
#pragma unroll
            for (int mi = 0; mi < 4; mi++)
#pragma unroll
                for (int nj = 0; nj < 4; nj++) {
                    mma_f16(acc[mi][nj * 2 + 0], af[cur][mi], bf[cur][nj][0], bf[cur][nj][1]);
                    mma_f16(acc[mi][nj * 2 + 1], af[cur][mi], bf[cur][nj][2], bf[cur][nj][3]);
                }
        }

        // stage release: everyone done reading slot cs (tensor pipe drains
        // the 16 just-issued MMAs while warps sit here)
        __syncthreads();

        // refill slot cs with k-iter kt+STAGES (disjoint from slot ncs read above)
        if (tid == 0 && kt + STAGES < K_ITERS) {
            const int li = kt + STAGES;
            MBAR_EXPECT_TX(sb + SMEM_FULL(cs), A_STAGE_B + B_STAGE_B);
            TMA_LOAD_2D(sb + SMEM_A_OFF + cs * A_STAGE_B, &tma_a, li * TK, m0,
                        sb + SMEM_FULL(cs));
            TMA_LOAD_2D(sb + SMEM_B_OFF + cs * B_STAGE_B, &tma_b, li * TK, n0,
                        sb + SMEM_FULL(cs));
        }

        cs = ncs; cph = nph;
    }

    // epilogue
    const int crow = lane >> 2;
    const int ccol = (lane & 3) * 2;
#pragma unroll
    for (int mi = 0; mi < 4; mi++) {
#pragma unroll
        for (int ni = 0; ni < 8; ni++) {
            const size_t m = (size_t)m0 + wm + mi * 16 + crow;
            const int n = n0 + wn + ni * 8 + ccol;
            float2 v0 = {acc[mi][ni][0], acc[mi][ni][1]};
            float2 v1 = {acc[mi][ni][2], acc[mi][ni][3]};
            *reinterpret_cast<float2*>(C + m * D_OUT + n) = v0;
            *reinterpret_cast<float2*>(C + (m + 8) * D_OUT + n) = v1;
        }
    }
}

// ---------------------------------------------------------------------------
// Host side
// ---------------------------------------------------------------------------
typedef CUresult (*EncodeFn)(CUtensorMap*, CUtensorMapDataType, cuuint32_t, void*,
                             const cuuint64_t*, const cuuint64_t*, const cuuint32_t*,
                             const cuuint32_t*, CUtensorMapInterleave, CUtensorMapSwizzle,
                             CUtensorMapL2promotion, CUtensorMapFloatOOBfill);

static EncodeFn get_encode_fn() {
    void* fn = nullptr;
    cudaDriverEntryPointQueryResult st;
#if CUDART_VERSION >= 12050
    cudaGetDriverEntryPointByVersion("cuTensorMapEncodeTiled", &fn, 12000,
                                     cudaEnableDefault, &st);
#else
    cudaGetDriverEntryPoint("cuTensorMapEncodeTiled", &fn, cudaEnableDefault, &st);
#endif
    return (EncodeFn)fn;
}

static void encode_2d_f16(EncodeFn fn, CUtensorMap* tm, void* ptr,
                          uint64_t dim0, uint64_t dim1, uint32_t box0, uint32_t box1) {
    cuuint64_t dims[2] = {dim0, dim1};
    cuuint64_t strides[1] = {dim0 * 2};
    cuuint32_t box[2] = {box0, box1};
    cuuint32_t es[2] = {1, 1};
    fn(tm, CU_TENSOR_MAP_DATA_TYPE_FLOAT16, 2, ptr, dims, strides, box, es,
       CU_TENSOR_MAP_INTERLEAVE_NONE, CU_TENSOR_MAP_SWIZZLE_128B,
       CU_TENSOR_MAP_L2_PROMOTION_L2_128B, CU_TENSOR_MAP_FLOAT_OOB_FILL_NONE);
}

extern "C" void kernel_launch(void* const* d_in, const int* in_sizes, int n_in,
                              void* d_out, int out_size) {
    const float* x  = (const float*)d_in[0];
    const int*   q  = (const int*)d_in[1];
    const float* ws = (const float*)d_in[2];
    const float* lA = (const float*)d_in[3];
    const float* lB = (const float*)d_in[4];
    float* out = (float*)d_out;

    __half* wh = nullptr;
    __half* xh = nullptr;
    cudaGetSymbolAddress((void**)&wh, g_wh);
    cudaGetSymbolAddress((void**)&xh, g_xh);

    convert_x_kernel<<<2048, 256>>>((const float4*)x, (uint2*)xh,
                                    (int)((size_t)M_TOT * D_IN / 4));
    dim3 pgrid(D_IN / 64, D_OUT / 64);
    prep_weff_kernel<<<pgrid, 256>>>(q, ws, lA, lB, (uint2*)wh);

    EncodeFn enc = get_encode_fn();
    CUtensorMap tm_a, tm_b;
    encode_2d_f16(enc, &tm_a, xh, D_IN, M_TOT, TK, TM);
    encode_2d_f16(enc, &tm_b, wh, D_IN, D_OUT, TK, TN);

    cudaFuncSetAttribute(gemm_f16_kernel,
                         cudaFuncAttributeMaxDynamicSharedMemorySize, SMEM_BYTES);
    gemm_f16_kernel<<<M_TILES * N_TILES, 128, SMEM_BYTES>>>(tm_a, tm_b, out);
}

// round 12
// speedup vs baseline: 1.0859x; 1.0164x over previous
#include <cuda_runtime.h>
#include <cuda.h>
#include <cuda_fp16.h>
#include <cstdint>

// ---------------------------------------------------------------------------
// Problem constants
// ---------------------------------------------------------------------------
#define D_IN   4096
#define D_OUT  4096
#define M_TOT  8192
#define RANK   64

// GEMM tiling (fp16 operands, fp32 accumulate)
#define TM 128
#define TN 128
#define TK 64                        // halves per K-stage = 128 B (one SW128 row)
#define STAGES 3
#define K_ITERS (D_IN / TK)          // 64
#define M_TILES (M_TOT / TM)         // 64
#define N_TILES (D_OUT / TN)         // 32

#define A_STAGE_B (TM * 128)         // 16384 bytes
#define B_STAGE_B (TN * 128)         // 16384 bytes
#define SMEM_FULL(s)  ((s) * 8)
#define SMEM_A_OFF    1024
#define SMEM_B_OFF    (SMEM_A_OFF + STAGES * A_STAGE_B)     // 50176
#define SMEM_BYTES    (SMEM_B_OFF + STAGES * B_STAGE_B)     // 99328 -> 2 CTAs/SM

// ---------------------------------------------------------------------------
// Device globals (allocation-free scratch)
// ---------------------------------------------------------------------------
__constant__ float c_nf4[16] = {
    -1.0f, -0.6962f, -0.5251f, -0.3949f, -0.2844f, -0.1848f,
    -0.0911f, 0.0f, 0.0796f, 0.1609f, 0.2461f, 0.3379f,
    0.4407f, 0.5626f, 0.723f, 1.0f};

__device__ __align__(1024) __half g_wh[(size_t)D_OUT * D_IN];  // W_eff fp16
__device__ __align__(1024) __half g_xh[(size_t)M_TOT * D_IN];  // x fp16
__device__ __align__(1024) __half g_lh[(size_t)D_OUT * D_IN];  // L = B@A fp16

// ---------------------------------------------------------------------------
// PTX helpers
// ---------------------------------------------------------------------------
#define LDMATRIX_X4(r0, r1, r2, r3, addr)                                     \
    asm volatile("ldmatrix.sync.aligned.m8n8.x4.shared.b16 {%0,%1,%2,%3}, [%4];" \
                 : "=r"(r0), "=r"(r1), "=r"(r2), "=r"(r3) : "r"(addr))

__device__ __forceinline__ void mma_f16(float* c, const uint32_t* a,
                                        uint32_t b0, uint32_t b1) {
    asm volatile(
        "mma.sync.aligned.m16n8k16.row.col.f32.f16.f16.f32 "
        "{%0,%1,%2,%3}, {%4,%5,%6,%7}, {%8,%9}, {%0,%1,%2,%3};"
        : "+f"(c[0]), "+f"(c[1]), "+f"(c[2]), "+f"(c[3])
        : "r"(a[0]), "r"(a[1]), "r"(a[2]), "r"(a[3]), "r"(b0), "r"(b1));
}

#define MBAR_INIT(addr, cnt) \
    asm volatile("mbarrier.init.shared.b64 [%0], %1;" :: "r"(addr), "r"(cnt) : "memory")

#define MBAR_EXPECT_TX(addr, bytes) \
    asm volatile("mbarrier.arrive.expect_tx.shared.b64 _, [%0], %1;" \
                 :: "r"(addr), "r"(bytes) : "memory")

#define MBAR_WAIT(addr, ph) do {                                                  \
    uint32_t _d = 0;                                                              \
    do {                                                                          \
        asm volatile("{\n\t.reg .pred P;\n\t"                                     \
            "mbarrier.try_wait.parity.acquire.cta.shared::cta.b64 P, [%1], %2, 0x989680;\n\t" \
            "selp.b32 %0, 1, 0, P;\n\t}"                                          \
            : "=r"(_d) : "r"(addr), "r"(ph) : "memory");                          \
    } while (!_d);                                                                \
} while (0)

#define TMA_LOAD_2D(smem_addr, tmap, cx, cy, mbar) \
    asm volatile( \
        "cp.async.bulk.tensor.2d.shared::cta.global.tile.mbarrier::complete_tx::bytes " \
        "[%0], [%1, {%2, %3}], [%4];" \
        :: "r"(smem_addr), "l"(tmap), "r"(cx), "r"(cy), "r"(mbar) : "memory")

__device__ __forceinline__ uint32_t h2_bits(__half2 h) {
    return *reinterpret_cast<uint32_t*>(&h);
}

// ---------------------------------------------------------------------------
// Prep 1: convert x to fp16
// ---------------------------------------------------------------------------
__global__ __launch_bounds__(256) void convert_x_kernel(const float4* __restrict__ x,
                                                        uint2* __restrict__ xh, int n4) {
    int i = blockIdx.x * blockDim.x + threadIdx.x;
    int stride = gridDim.x * blockDim.x;
    for (; i < n4; i += stride) {
        float4 v = x[i];
        uint2 o;
        o.x = h2_bits(__floats2half2_rn(v.x, v.y));
        o.y = h2_bits(__floats2half2_rn(v.z, v.w));
        xh[i] = o;
    }
}

// ---------------------------------------------------------------------------
// Prep 2a: L[o,i] = sum_r B[o,r] * A[r,i] via fp16 HMMA (K=RANK=64, one shot)
// CTA: 128(o) x 64(i); 4 warps 2x2 of 64x32 warp tiles. Padded smem (R4 style).
// ---------------------------------------------------------------------------
#define LROWH 72     // 64 + 8 pad halves = 144 B rows, conflict-free
__global__ __launch_bounds__(128) void lora_kernel(
    const float* __restrict__ lA, const float* __restrict__ lB,
    __half* __restrict__ L) {
    __shared__ __half sB[128][LROWH];    // o x r   (mma A operand, row.col -> row major m x k)
    __shared__ __half sAt[64][LROWH];    // i x r   (mma B operand, col major n x k)
    const int tid = threadIdx.x;
    const int o0 = blockIdx.y * 128;
    const int i0 = blockIdx.x * 64;

    for (int idx = tid; idx < 128 * RANK; idx += 128) {
        int o = idx >> 6, r = idx & 63;
        sB[o][r] = __float2half(lB[(size_t)(o0 + o) * RANK + r]);
    }
    for (int idx = tid; idx < 64 * RANK; idx += 128) {
        int r = idx >> 6, i = idx & 63;
        sAt[i][r] = __float2half(lA[(size_t)r * D_IN + i0 + i]);
    }
    __syncthreads();

    const int warp = tid >> 5;
    const int lane = tid & 31;
    const int wm = (warp & 1) * 64;      // o offset
    const int wn = (warp >> 1) * 32;     // i offset

    const int lg = lane >> 3;
    const int lr = lane & 7;
    const int a_row = lr + (lg & 1) * 8;
    const int a_kof = (lg >> 1) * 8;
    const int b_row = lr + (lg >> 1) * 8;
    const int b_kof = (lg & 1) * 8;

    const uint32_t sb_base = (uint32_t)__cvta_generic_to_shared(&sB[0][0]);
    const uint32_t sa_base = (uint32_t)__cvta_generic_to_shared(&sAt[0][0]);

    float acc[4][4][4] = {};
#pragma unroll
    for (int kk = 0; kk < 4; kk++) {
        const int k0 = kk * 16;
        uint32_t af[4][4];
#pragma unroll
        for (int mi = 0; mi < 4; mi++) {
            uint32_t addr = sb_base + ((wm + mi * 16 + a_row) * LROWH + k0 + a_kof) * 2;
            LDMATRIX_X4(af[mi][0], af[mi][1], af[mi][2], af[mi][3], addr);
        }
        uint32_t bfr[2][4];
#pragma unroll
        for (int nj = 0; nj < 2; nj++) {
            uint32_t addr = sa_base + ((wn + nj * 16 + b_row) * LROWH + k0 + b_kof) * 2;
            LDMATRIX_X4(bfr[nj][0], bfr[nj][1], bfr[nj][2], bfr[nj][3], addr);
        }
#pragma unroll
        for (int mi = 0; mi < 4; mi++)
#pragma unroll
            for (int nj = 0; nj < 2; nj++) {
                mma_f16(acc[mi][nj * 2 + 0], af[mi], bfr[nj][0], bfr[nj][1]);
                mma_f16(acc[mi][nj * 2 + 1], af[mi], bfr[nj][2], bfr[nj][3]);
            }
    }

    const int crow = lane >> 2;
    const int ccol = (lane & 3) * 2;
#pragma unroll
    for (int mi = 0; mi < 4; mi++) {
#pragma unroll
        for (int ni = 0; ni < 4; ni++) {
            const size_t o = o0 + wm + mi * 16 + crow;
            const int i = i0 + wn + ni * 8 + ccol;
            __half2 h0 = __floats2half2_rn(acc[mi][ni][0], acc[mi][ni][1]);
            __half2 h1 = __floats2half2_rn(acc[mi][ni][2], acc[mi][ni][3]);
            *reinterpret_cast<__half2*>(&L[o * D_IN + i]) = h0;
            *reinterpret_cast<__half2*>(&L[(o + 8) * D_IN + i]) = h1;
        }
    }
}

// ---------------------------------------------------------------------------
// Prep 2b: wh = fp16( NF4[q]*scale + 0.25 * L )   — pure elementwise, DRAM-bound
// ---------------------------------------------------------------------------
__global__ __launch_bounds__(256) void dequant_add_kernel(
    const int4* __restrict__ q4, const uint2* __restrict__ L4,
    const float* __restrict__ wscale, uint2* __restrict__ wh, int n4) {
    const float s = wscale[0];
    int i = blockIdx.x * blockDim.x + threadIdx.x;
    const int stride = gridDim.x * blockDim.x;
    for (; i < n4; i += stride) {
        const int4 qv = q4[i];
        const uint2 lv = L4[i];
        const __half2 l0 = *reinterpret_cast<const __half2*>(&lv.x);
        const __half2 l1 = *reinterpret_cast<const __half2*>(&lv.y);
        float f0 = c_nf4[qv.x & 15] * s + 0.25f * __low2float(l0);
        float f1 = c_nf4[qv.y & 15] * s + 0.25f * __high2float(l0);
        float f2 = c_nf4[qv.z & 15] * s + 0.25f * __low2float(l1);
        float f3 = c_nf4[qv.w & 15] * s + 0.25f * __high2float(l1);
        uint2 o;
        o.x = h2_bits(__floats2half2_rn(f0, f1));
        o.y = h2_bits(__floats2half2_rn(f2, f3));
        wh[i] = o;
    }
}

// ---------------------------------------------------------------------------
// Main GEMM: C[m,n] = sum_k Xh[m,k] * Wh[n,k]   (unchanged from R11)
// ---------------------------------------------------------------------------
__global__ void __launch_bounds__(128, 2)
gemm_f16_kernel(const __grid_constant__ CUtensorMap tma_a,
                const __grid_constant__ CUtensorMap tma_b,
                float* __restrict__ C) {
    extern __shared__ char smem[];
    const uint32_t sb = (uint32_t)__cvta_generic_to_shared(smem);

    const int tid = threadIdx.x;
    const int warp = tid >> 5;
    const int lane = tid & 31;

    const int bid = blockIdx.x;
    const int GROUP_M = 8;
    const int per_group = GROUP_M * N_TILES;
    const int g = bid / per_group, rem = bid % per_group;
    const int mt = g * GROUP_M + (rem % GROUP_M);
    const int nt = rem / GROUP_M;
    const int m0 = mt * TM, n0 = nt * TN;

    const int wm = (warp & 1) * 64;
    const int wn = (warp >> 1) * 64;

    if (tid == 0) {
        for (int s = 0; s < STAGES; s++)
            MBAR_INIT(sb + SMEM_FULL(s), 1);
        asm volatile("fence.proxy.async.shared::cta;" ::: "memory");
    }
    __syncthreads();

    if (tid == 0) {
#pragma unroll
        for (int s = 0; s < STAGES; s++) {
            MBAR_EXPECT_TX(sb + SMEM_FULL(s), A_STAGE_B + B_STAGE_B);
            TMA_LOAD_2D(sb + SMEM_A_OFF + s * A_STAGE_B, &tma_a, s * TK, m0,
                        sb + SMEM_FULL(s));
            TMA_LOAD_2D(sb + SMEM_B_OFF + s * B_STAGE_B, &tma_b, s * TK, n0,
                        sb + SMEM_FULL(s));
        }
    }

    float acc[4][8][4];
#pragma unroll
    for (int mi = 0; mi < 4; mi++)
#pragma unroll
        for (int ni = 0; ni < 8; ni++)
#pragma unroll
            for (int c = 0; c < 4; c++) acc[mi][ni][c] = 0.f;

    const int lg = lane >> 3;
    const int lr = lane & 7;
    const int a_row = lr + (lg & 1) * 8;
    const int a_kch = lg >> 1;
    const int b_row = lr + (lg >> 1) * 8;
    const int b_kch = lg & 1;

    uint32_t af[2][4][4];
    uint32_t bf[2][4][4];

    auto load_frag = [&](int buf, uint32_t a_st, uint32_t b_st, int kk) {
#pragma unroll
        for (int mi = 0; mi < 4; mi++) {
            const int row = wm + mi * 16 + a_row;
            const int ch = (2 * kk + a_kch) ^ (row & 7);
            uint32_t addr = a_st + row * 128 + ch * 16;
            LDMATRIX_X4(af[buf][mi][0], af[buf][mi][1], af[buf][mi][2], af[buf][mi][3], addr);
        }
#pragma unroll
        for (int nj = 0; nj < 4; nj++) {
            const int row = wn + nj * 16 + b_row;
            const int ch = (2 * kk + b_kch) ^ (row & 7);
            uint32_t addr = b_st + row * 128 + ch * 16;
            LDMATRIX_X4(bf[buf][nj][0], bf[buf][nj][1], bf[buf][nj][2], bf[buf][nj][3], addr);
        }
    };

    int cs = 0, cph = 0;

    MBAR_WAIT(sb + SMEM_FULL(0), 0);
    load_frag(0, sb + SMEM_A_OFF, sb + SMEM_B_OFF, 0);

    for (int kt = 0; kt < K_ITERS; kt++) {
        const uint32_t a_st = sb + SMEM_A_OFF + cs * A_STAGE_B;
        const uint32_t b_st = sb + SMEM_B_OFF + cs * B_STAGE_B;

        const int ncs = (cs + 1 == STAGES) ? 0 : cs + 1;
        const int nph = (cs + 1 == STAGES) ? (cph ^ 1) : cph;

#pragma unroll
        for (int kk = 0; kk < 4; kk++) {
            const int cur = kk & 1;
            if (kk < 3) {
                load_frag(cur ^ 1, a_st, b_st, kk + 1);
            } else if (kt + 1 < K_ITERS) {
                MBAR_WAIT(sb + SMEM_FULL(ncs), nph);
                load_frag(cur ^ 1, sb + SMEM_A_OFF + ncs * A_STAGE_B,
                          sb + SMEM_B_OFF + ncs * B_STAGE_B, 0);
            }
#pragma unroll
            for (int mi = 0; mi < 4; mi++)
#pragma unroll
                for (int nj = 0; nj < 4; nj++) {
                    mma_f16(acc[mi][nj * 2 + 0], af[cur][mi], bf[cur][nj][0], bf[cur][nj][1]);
                    mma_f16(acc[mi][nj * 2 + 1], af[cur][mi], bf[cur][nj][2], bf[cur][nj][3]);
                }
        }

        __syncthreads();

        if (tid == 0 && kt + STAGES < K_ITERS) {
            const int li = kt + STAGES;
            MBAR_EXPECT_TX(sb + SMEM_FULL(cs), A_STAGE_B + B_STAGE_B);
            TMA_LOAD_2D(sb + SMEM_A_OFF + cs * A_STAGE_B, &tma_a, li * TK, m0,
                        sb + SMEM_FULL(cs));
            TMA_LOAD_2D(sb + SMEM_B_OFF + cs * B_STAGE_B, &tma_b, li * TK, n0,
                        sb + SMEM_FULL(cs));
        }

        cs = ncs; cph = nph;
    }

    const int crow = lane >> 2;
    const int ccol = (lane & 3) * 2;
#pragma unroll
    for (int mi = 0; mi < 4; mi++) {
#pragma unroll
        for (int ni = 0; ni < 8; ni++) {
            const size_t m = (size_t)m0 + wm + mi * 16 + crow;
            const int n = n0 + wn + ni * 8 + ccol;
            float2 v0 = {acc[mi][ni][0], acc[mi][ni][1]};
            float2 v1 = {acc[mi][ni][2], acc[mi][ni][3]};
            *reinterpret_cast<float2*>(C + m * D_OUT + n) = v0;
            *reinterpret_cast<float2*>(C + (m + 8) * D_OUT + n) = v1;
        }
    }
}

// ---------------------------------------------------------------------------
// Host side
// ---------------------------------------------------------------------------
typedef CUresult (*EncodeFn)(CUtensorMap*, CUtensorMapDataType, cuuint32_t, void*,
                             const cuuint64_t*, const cuuint64_t*, const cuuint32_t*,
                             const cuuint32_t*, CUtensorMapInterleave, CUtensorMapSwizzle,
                             CUtensorMapL2promotion, CUtensorMapFloatOOBfill);

static EncodeFn get_encode_fn() {
    void* fn = nullptr;
    cudaDriverEntryPointQueryResult st;
#if CUDART_VERSION >= 12050
    cudaGetDriverEntryPointByVersion("cuTensorMapEncodeTiled", &fn, 12000,
                                     cudaEnableDefault, &st);
#else
    cudaGetDriverEntryPoint("cuTensorMapEncodeTiled", &fn, cudaEnableDefault, &st);
#endif
    return (EncodeFn)fn;
}

static void encode_2d_f16(EncodeFn fn, CUtensorMap* tm, void* ptr,
                          uint64_t dim0, uint64_t dim1, uint32_t box0, uint32_t box1) {
    cuuint64_t dims[2] = {dim0, dim1};
    cuuint64_t strides[1] = {dim0 * 2};
    cuuint32_t box[2] = {box0, box1};
    cuuint32_t es[2] = {1, 1};
    fn(tm, CU_TENSOR_MAP_DATA_TYPE_FLOAT16, 2, ptr, dims, strides, box, es,
       CU_TENSOR_MAP_INTERLEAVE_NONE, CU_TENSOR_MAP_SWIZZLE_128B,
       CU_TENSOR_MAP_L2_PROMOTION_L2_128B, CU_TENSOR_MAP_FLOAT_OOB_FILL_NONE);
}

extern "C" void kernel_launch(void* const* d_in, const int* in_sizes, int n_in,
                              void* d_out, int out_size) {
    const float* x  = (const float*)d_in[0];
    const int*   q  = (const int*)d_in[1];
    const float* ws = (const float*)d_in[2];
    const float* lA = (const float*)d_in[3];
    const float* lB = (const float*)d_in[4];
    float* out = (float*)d_out;

    __half* wh = nullptr;
    __half* xh = nullptr;
    __half* lh = nullptr;
    cudaGetSymbolAddress((void**)&wh, g_wh);
    cudaGetSymbolAddress((void**)&xh, g_xh);
    cudaGetSymbolAddress((void**)&lh, g_lh);

    convert_x_kernel<<<2048, 256>>>((const float4*)x, (uint2*)xh,
                                    (int)((size_t)M_TOT * D_IN / 4));
    dim3 lgrid(D_IN / 64, D_OUT / 128);
    lora_kernel<<<lgrid, 128>>>(lA, lB, lh);
    dequant_add_kernel<<<2048, 256>>>((const int4*)q, (const uint2*)lh, ws,
                                      (uint2*)wh, (int)((size_t)D_OUT * D_IN / 4));

    EncodeFn enc = get_encode_fn();
    CUtensorMap tm_a, tm_b;
    encode_2d_f16(enc, &tm_a, xh, D_IN, M_TOT, TK, TM);
    encode_2d_f16(enc, &tm_b, wh, D_IN, D_OUT, TK, TN);

    cudaFuncSetAttribute(gemm_f16_kernel,
                         cudaFuncAttributeMaxDynamicSharedMemorySize, SMEM_BYTES);
    gemm_f16_kernel<<<M_TILES * N_TILES, 128, SMEM_BYTES>>>(tm_a, tm_b, out);
}

// round 13
// speedup vs baseline: 1.1703x; 1.0777x over previous
#include <cuda_runtime.h>
#include <cuda.h>
#include <cuda_fp16.h>
#include <cstdint>

// ---------------------------------------------------------------------------
// Problem constants
// ---------------------------------------------------------------------------
#define D_IN   4096
#define D_OUT  4096
#define M_TOT  8192
#define RANK   64

// GEMM tiling (fp16 operands, fp32 accumulate)
#define TM 128
#define TN 128
#define TK 64                        // halves per K-stage = 128 B (one SW128 row)
#define STAGES 3
#define K_ITERS (D_IN / TK)          // 64
#define M_TILES (M_TOT / TM)         // 64
#define N_TILES (D_OUT / TN)         // 32

#define A_STAGE_B (TM * 128)         // 16384 bytes
#define B_STAGE_B (TN * 128)         // 16384 bytes
#define SMEM_FULL(s)  ((s) * 8)
#define SMEM_A_OFF    1024
#define SMEM_B_OFF    (SMEM_A_OFF + STAGES * A_STAGE_B)     // 50176
#define SMEM_BYTES    (SMEM_B_OFF + STAGES * B_STAGE_B)     // 99328 -> 2 CTAs/SM

// ---------------------------------------------------------------------------
// Device globals (allocation-free scratch)
// ---------------------------------------------------------------------------
__constant__ float c_nf4[16] = {
    -1.0f, -0.6962f, -0.5251f, -0.3949f, -0.2844f, -0.1848f,
    -0.0911f, 0.0f, 0.0796f, 0.1609f, 0.2461f, 0.3379f,
    0.4407f, 0.5626f, 0.723f, 1.0f};

__device__ __align__(1024) __half g_wh[(size_t)D_OUT * D_IN];  // W_eff fp16
__device__ __align__(1024) __half g_xh[(size_t)M_TOT * D_IN];  // x fp16

// ---------------------------------------------------------------------------
// PTX helpers
// ---------------------------------------------------------------------------
#define LDMATRIX_X4(r0, r1, r2, r3, addr)                                     \
    asm volatile("ldmatrix.sync.aligned.m8n8.x4.shared.b16 {%0,%1,%2,%3}, [%4];" \
                 : "=r"(r0), "=r"(r1), "=r"(r2), "=r"(r3) : "r"(addr))

__device__ __forceinline__ void mma_f16(float* c, const uint32_t* a,
                                        uint32_t b0, uint32_t b1) {
    asm volatile(
        "mma.sync.aligned.m16n8k16.row.col.f32.f16.f16.f32 "
        "{%0,%1,%2,%3}, {%4,%5,%6,%7}, {%8,%9}, {%0,%1,%2,%3};"
        : "+f"(c[0]), "+f"(c[1]), "+f"(c[2]), "+f"(c[3])
        : "r"(a[0]), "r"(a[1]), "r"(a[2]), "r"(a[3]), "r"(b0), "r"(b1));
}

#define MBAR_INIT(addr, cnt) \
    asm volatile("mbarrier.init.shared.b64 [%0], %1;" :: "r"(addr), "r"(cnt) : "memory")

#define MBAR_EXPECT_TX(addr, bytes) \
    asm volatile("mbarrier.arrive.expect_tx.shared.b64 _, [%0], %1;" \
                 :: "r"(addr), "r"(bytes) : "memory")

#define MBAR_WAIT(addr, ph) do {                                                  \
    uint32_t _d = 0;                                                              \
    do {                                                                          \
        asm volatile("{\n\t.reg .pred P;\n\t"                                     \
            "mbarrier.try_wait.parity.acquire.cta.shared::cta.b64 P, [%1], %2, 0x989680;\n\t" \
            "selp.b32 %0, 1, 0, P;\n\t}"                                          \
            : "=r"(_d) : "r"(addr), "r"(ph) : "memory");                          \
    } while (!_d);                                                                \
} while (0)

#define TMA_LOAD_2D(smem_addr, tmap, cx, cy, mbar) \
    asm volatile( \
        "cp.async.bulk.tensor.2d.shared::cta.global.tile.mbarrier::complete_tx::bytes " \
        "[%0], [%1, {%2, %3}], [%4];" \
        :: "r"(smem_addr), "l"(tmap), "r"(cx), "r"(cy), "r"(mbar) : "memory")

__device__ __forceinline__ uint32_t h2_bits(__half2 h) {
    return *reinterpret_cast<uint32_t*>(&h);
}

// ---------------------------------------------------------------------------
// Prep 1: convert x to fp16
// ---------------------------------------------------------------------------
__global__ __launch_bounds__(256) void convert_x_kernel(const float4* __restrict__ x,
                                                        uint2* __restrict__ xh, int n4) {
    int i = blockIdx.x * blockDim.x + threadIdx.x;
    int stride = gridDim.x * blockDim.x;
    for (; i < n4; i += stride) {
        float4 v = x[i];
        uint2 o;
        o.x = h2_bits(__floats2half2_rn(v.x, v.y));
        o.y = h2_bits(__floats2half2_rn(v.z, v.w));
        xh[i] = o;
    }
}

// ---------------------------------------------------------------------------
// Prep 2 (fused): per 128(o) x 64(i) tile:
//   phase 1: L = B@A via fp16 HMMA (K=RANK=64, one shot)
//   phase 2: wh = fp16( NF4[q]*scale + 0.25*L ), NF4 via lane-shuffle LUT
// ---------------------------------------------------------------------------
#define LROWH 72     // 64 + 8 pad halves = 144 B rows, conflict-free
__global__ __launch_bounds__(128) void lora_dequant_kernel(
    const float* __restrict__ lA, const float* __restrict__ lB,
    const int* __restrict__ q, const float* __restrict__ wscale,
    __half* __restrict__ wh) {
    __shared__ __half sB[128][LROWH];    // o x r   (mma A operand, m x k row-major)
    __shared__ __half sAt[64][LROWH];    // i x r   (mma B operand, n x k col-major)
    const int tid = threadIdx.x;
    const int o0 = blockIdx.y * 128;
    const int i0 = blockIdx.x * 64;

    for (int idx = tid; idx < 128 * RANK; idx += 128) {
        int o = idx >> 6, r = idx & 63;
        sB[o][r] = __float2half(lB[(size_t)(o0 + o) * RANK + r]);
    }
    for (int idx = tid; idx < 64 * RANK; idx += 128) {
        int r = idx >> 6, i = idx & 63;
        sAt[i][r] = __float2half(lA[(size_t)r * D_IN + i0 + i]);
    }
    __syncthreads();

    const int warp = tid >> 5;
    const int lane = tid & 31;
    const int wm = (warp & 1) * 64;      // o offset
    const int wn = (warp >> 1) * 32;     // i offset

    const int lg = lane >> 3;
    const int lr = lane & 7;
    const int a_row = lr + (lg & 1) * 8;
    const int a_kof = (lg >> 1) * 8;
    const int b_row = lr + (lg >> 1) * 8;
    const int b_kof = (lg & 1) * 8;

    const uint32_t sb_base = (uint32_t)__cvta_generic_to_shared(&sB[0][0]);
    const uint32_t sa_base = (uint32_t)__cvta_generic_to_shared(&sAt[0][0]);

    float acc[4][4][4] = {};
#pragma unroll
    for (int kk = 0; kk < 4; kk++) {
        const int k0 = kk * 16;
        uint32_t af[4][4];
#pragma unroll
        for (int mi = 0; mi < 4; mi++) {
            uint32_t addr = sb_base + ((wm + mi * 16 + a_row) * LROWH + k0 + a_kof) * 2;
            LDMATRIX_X4(af[mi][0], af[mi][1], af[mi][2], af[mi][3], addr);
        }
        uint32_t bfr[2][4];
#pragma unroll
        for (int nj = 0; nj < 2; nj++) {
            uint32_t addr = sa_base + ((wn + nj * 16 + b_row) * LROWH + k0 + b_kof) * 2;
            LDMATRIX_X4(bfr[nj][0], bfr[nj][1], bfr[nj][2], bfr[nj][3], addr);
        }
#pragma unroll
        for (int mi = 0; mi < 4; mi++)
#pragma unroll
            for (int nj = 0; nj < 2; nj++) {
                mma_f16(acc[mi][nj * 2 + 0], af[mi], bfr[nj][0], bfr[nj][1]);
                mma_f16(acc[mi][nj * 2 + 1], af[mi], bfr[nj][2], bfr[nj][3]);
            }
    }

    // phase 2: dequant + add, NF4 via lane shuffle (no LDC replay)
    const float nf4_lane = c_nf4[lane & 15];
    const float s = wscale[0];
    const int crow = lane >> 2;
    const int ccol = (lane & 3) * 2;
#pragma unroll
    for (int mi = 0; mi < 4; mi++) {
#pragma unroll
        for (int ni = 0; ni < 4; ni++) {
            const size_t o = o0 + wm + mi * 16 + crow;
            const int i = i0 + wn + ni * 8 + ccol;
            const int2 q0 = *reinterpret_cast<const int2*>(&q[o * D_IN + i]);
            const int2 q1 = *reinterpret_cast<const int2*>(&q[(o + 8) * D_IN + i]);
            float f0 = __shfl_sync(0xffffffffu, nf4_lane, q0.x & 15) * s + 0.25f * acc[mi][ni][0];
            float f1 = __shfl_sync(0xffffffffu, nf4_lane, q0.y & 15) * s + 0.25f * acc[mi][ni][1];
            float f2 = __shfl_sync(0xffffffffu, nf4_lane, q1.x & 15) * s + 0.25f * acc[mi][ni][2];
            float f3 = __shfl_sync(0xffffffffu, nf4_lane, q1.y & 15) * s + 0.25f * acc[mi][ni][3];
            *reinterpret_cast<__half2*>(&wh[o * D_IN + i]) = __floats2half2_rn(f0, f1);
            *reinterpret_cast<__half2*>(&wh[(o + 8) * D_IN + i]) = __floats2half2_rn(f2, f3);
        }
    }
}

// ---------------------------------------------------------------------------
// Main GEMM: C[m,n] = sum_k Xh[m,k] * Wh[n,k]   (unchanged — at issue roofline)
// ---------------------------------------------------------------------------
__global__ void __launch_bounds__(128, 2)
gemm_f16_kernel(const __grid_constant__ CUtensorMap tma_a,
                const __grid_constant__ CUtensorMap tma_b,
                float* __restrict__ C) {
    extern __shared__ char smem[];
    const uint32_t sb = (uint32_t)__cvta_generic_to_shared(smem);

    const int tid = threadIdx.x;
    const int warp = tid >> 5;
    const int lane = tid & 31;

    const int bid = blockIdx.x;
    const int GROUP_M = 8;
    const int per_group = GROUP_M * N_TILES;
    const int g = bid / per_group, rem = bid % per_group;
    const int mt = g * GROUP_M + (rem % GROUP_M);
    const int nt = rem / GROUP_M;
    const int m0 = mt * TM, n0 = nt * TN;

    const int wm = (warp & 1) * 64;
    const int wn = (warp >> 1) * 64;

    if (tid == 0) {
        for (int s = 0; s < STAGES; s++)
            MBAR_INIT(sb + SMEM_FULL(s), 1);
        asm volatile("fence.proxy.async.shared::cta;" ::: "memory");
    }
    __syncthreads();

    if (tid == 0) {
#pragma unroll
        for (int s = 0; s < STAGES; s++) {
            MBAR_EXPECT_TX(sb + SMEM_FULL(s), A_STAGE_B + B_STAGE_B);
            TMA_LOAD_2D(sb + SMEM_A_OFF + s * A_STAGE_B, &tma_a, s * TK, m0,
                        sb + SMEM_FULL(s));
            TMA_LOAD_2D(sb + SMEM_B_OFF + s * B_STAGE_B, &tma_b, s * TK, n0,
                        sb + SMEM_FULL(s));
        }
    }

    float acc[4][8][4];
#pragma unroll
    for (int mi = 0; mi < 4; mi++)
#pragma unroll
        for (int ni = 0; ni < 8; ni++)
#pragma unroll
            for (int c = 0; c < 4; c++) acc[mi][ni][c] = 0.f;

    const int lg = lane >> 3;
    const int lr = lane & 7;
    const int a_row = lr + (lg & 1) * 8;
    const int a_kch = lg >> 1;
    const int b_row = lr + (lg >> 1) * 8;
    const int b_kch = lg & 1;

    uint32_t af[2][4][4];
    uint32_t bf[2][4][4];

    auto load_frag = [&](int buf, uint32_t a_st, uint32_t b_st, int kk) {
#pragma unroll
        for (int mi = 0; mi < 4; mi++) {
            const int row = wm + mi * 16 + a_row;
            const int ch = (2 * kk + a_kch) ^ (row & 7);
            uint32_t addr = a_st + row * 128 + ch * 16;
            LDMATRIX_X4(af[buf][mi][0], af[buf][mi][1], af[buf][mi][2], af[buf][mi][3], addr);
        }
#pragma unroll
        for (int nj = 0; nj < 4; nj++) {
            const int row = wn + nj * 16 + b_row;
            const int ch = (2 * kk + b_kch) ^ (row & 7);
            uint32_t addr = b_st + row * 128 + ch * 16;
            LDMATRIX_X4(bf[buf][nj][0], bf[buf][nj][1], bf[buf][nj][2], bf[buf][nj][3], addr);
        }
    };

    int cs = 0, cph = 0;

    MBAR_WAIT(sb + SMEM_FULL(0), 0);
    load_frag(0, sb + SMEM_A_OFF, sb + SMEM_B_OFF, 0);

    for (int kt = 0; kt < K_ITERS; kt++) {
        const uint32_t a_st = sb + SMEM_A_OFF + cs * A_STAGE_B;
        const uint32_t b_st = sb + SMEM_B_OFF + cs * B_STAGE_B;

        const int ncs = (cs + 1 == STAGES) ? 0 : cs + 1;
        const int nph = (cs + 1 == STAGES) ? (cph ^ 1) : cph;

#pragma unroll
        for (int kk = 0; kk < 4; kk++) {
            const int cur = kk & 1;
            if (kk < 3) {
                load_frag(cur ^ 1, a_st, b_st, kk + 1);
            } else if (kt + 1 < K_ITERS) {
                MBAR_WAIT(sb + SMEM_FULL(ncs), nph);
                load_frag(cur ^ 1, sb + SMEM_A_OFF + ncs * A_STAGE_B,
                          sb + SMEM_B_OFF + ncs * B_STAGE_B, 0);
            }
#pragma unroll
            for (int mi = 0; mi < 4; mi++)
#pragma unroll
                for (int nj = 0; nj < 4; nj++) {
                    mma_f16(acc[mi][nj * 2 + 0], af[cur][mi], bf[cur][nj][0], bf[cur][nj][1]);
                    mma_f16(acc[mi][nj * 2 + 1], af[cur][mi], bf[cur][nj][2], bf[cur][nj][3]);
                }
        }

        __syncthreads();

        if (tid == 0 && kt + STAGES < K_ITERS) {
            const int li = kt + STAGES;
            MBAR_EXPECT_TX(sb + SMEM_FULL(cs), A_STAGE_B + B_STAGE_B);
            TMA_LOAD_2D(sb + SMEM_A_OFF + cs * A_STAGE_B, &tma_a, li * TK, m0,
                        sb + SMEM_FULL(cs));
            TMA_LOAD_2D(sb + SMEM_B_OFF + cs * B_STAGE_B, &tma_b, li * TK, n0,
                        sb + SMEM_FULL(cs));
        }

        cs = ncs; cph = nph;
    }

    const int crow = lane >> 2;
    const int ccol = (lane & 3) * 2;
#pragma unroll
    for (int mi = 0; mi < 4; mi++) {
#pragma unroll
        for (int ni = 0; ni < 8; ni++) {
            const size_t m = (size_t)m0 + wm + mi * 16 + crow;
            const int n = n0 + wn + ni * 8 + ccol;
            float2 v0 = {acc[mi][ni][0], acc[mi][ni][1]};
            float2 v1 = {acc[mi][ni][2], acc[mi][ni][3]};
            *reinterpret_cast<float2*>(C + m * D_OUT + n) = v0;
            *reinterpret_cast<float2*>(C + (m + 8) * D_OUT + n) = v1;
        }
    }
}

// ---------------------------------------------------------------------------
// Host side
// ---------------------------------------------------------------------------
typedef CUresult (*EncodeFn)(CUtensorMap*, CUtensorMapDataType, cuuint32_t, void*,
                             const cuuint64_t*, const cuuint64_t*, const cuuint32_t*,
                             const cuuint32_t*, CUtensorMapInterleave, CUtensorMapSwizzle,
                             CUtensorMapL2promotion, CUtensorMapFloatOOBfill);

static EncodeFn get_encode_fn() {
    void* fn = nullptr;
    cudaDriverEntryPointQueryResult st;
#if CUDART_VERSION >= 12050
    cudaGetDriverEntryPointByVersion("cuTensorMapEncodeTiled", &fn, 12000,
                                     cudaEnableDefault, &st);
#else
    cudaGetDriverEntryPoint("cuTensorMapEncodeTiled", &fn, cudaEnableDefault, &st);
#endif
    return (EncodeFn)fn;
}

static void encode_2d_f16(EncodeFn fn, CUtensorMap* tm, void* ptr,
                          uint64_t dim0, uint64_t dim1, uint32_t box0, uint32_t box1) {
    cuuint64_t dims[2] = {dim0, dim1};
    cuuint64_t strides[1] = {dim0 * 2};
    cuuint32_t box[2] = {box0, box1};
    cuuint32_t es[2] = {1, 1};
    fn(tm, CU_TENSOR_MAP_DATA_TYPE_FLOAT16, 2, ptr, dims, strides, box, es,
       CU_TENSOR_MAP_INTERLEAVE_NONE, CU_TENSOR_MAP_SWIZZLE_128B,
       CU_TENSOR_MAP_L2_PROMOTION_L2_128B, CU_TENSOR_MAP_FLOAT_OOB_FILL_NONE);
}

extern "C" void kernel_launch(void* const* d_in, const int* in_sizes, int n_in,
                              void* d_out, int out_size) {
    const float* x  = (const float*)d_in[0];
    const int*   q  = (const int*)d_in[1];
    const float* ws = (const float*)d_in[2];
    const float* lA = (const float*)d_in[3];
    const float* lB = (const float*)d_in[4];
    float* out = (float*)d_out;

    __half* wh = nullptr;
    __half* xh = nullptr;
    cudaGetSymbolAddress((void**)&wh, g_wh);
    cudaGetSymbolAddress((void**)&xh, g_xh);

    convert_x_kernel<<<2048, 256>>>((const float4*)x, (uint2*)xh,
                                    (int)((size_t)M_TOT * D_IN / 4));
    dim3 lgrid(D_IN / 64, D_OUT / 128);
    lora_dequant_kernel<<<lgrid, 128>>>(lA, lB, q, ws, wh);

    EncodeFn enc = get_encode_fn();
    CUtensorMap tm_a, tm_b;
    encode_2d_f16(enc, &tm_a, xh, D_IN, M_TOT, TK, TM);
    encode_2d_f16(enc, &tm_b, wh, D_IN, D_OUT, TK, TN);

    cudaFuncSetAttribute(gemm_f16_kernel,
                         cudaFuncAttributeMaxDynamicSharedMemorySize, SMEM_BYTES);
    gemm_f16_kernel<<<M_TILES * N_TILES, 128, SMEM_BYTES>>>(tm_a, tm_b, out);
}

// round 14
// speedup vs baseline: 1.2161x; 1.0391x over previous
#include <cuda_runtime.h>
#include <cuda.h>
#include <cuda_fp16.h>
#include <cstdint>

// ---------------------------------------------------------------------------
// Problem constants
// ---------------------------------------------------------------------------
#define D_IN   4096
#define D_OUT  4096
#define M_TOT  8192
#define RANK   64

// GEMM tiling (fp16 operands, fp32 accumulate)
#define TM 128
#define TN 128
#define TK 64                        // halves per K-stage = 128 B (one SW128 row)
#define STAGES 3
#define K_ITERS (D_IN / TK)          // 64
#define M_TILES (M_TOT / TM)         // 64
#define N_TILES (D_OUT / TN)         // 32

#define A_STAGE_B (TM * 128)         // 16384 bytes
#define B_STAGE_B (TN * 128)         // 16384 bytes
#define SMEM_FULL(s)  ((s) * 8)
#define SMEM_A_OFF    1024
#define SMEM_B_OFF    (SMEM_A_OFF + STAGES * A_STAGE_B)     // 50176
#define SMEM_BYTES    (SMEM_B_OFF + STAGES * B_STAGE_B)     // 99328 -> 2 CTAs/SM

// ---------------------------------------------------------------------------
// Device globals (allocation-free scratch)
// ---------------------------------------------------------------------------
__constant__ float c_nf4[16] = {
    -1.0f, -0.6962f, -0.5251f, -0.3949f, -0.2844f, -0.1848f,
    -0.0911f, 0.0f, 0.0796f, 0.1609f, 0.2461f, 0.3379f,
    0.4407f, 0.5626f, 0.723f, 1.0f};

__device__ __align__(1024) __half g_wh[(size_t)D_OUT * D_IN];  // W_eff fp16
__device__ __align__(1024) __half g_xh[(size_t)M_TOT * D_IN];  // x fp16

// ---------------------------------------------------------------------------
// PTX helpers
// ---------------------------------------------------------------------------
#define LDMATRIX_X4(r0, r1, r2, r3, addr)                                     \
    asm volatile("ldmatrix.sync.aligned.m8n8.x4.shared.b16 {%0,%1,%2,%3}, [%4];" \
                 : "=r"(r0), "=r"(r1), "=r"(r2), "=r"(r3) : "r"(addr))

__device__ __forceinline__ void mma_f16(float* c, const uint32_t* a,
                                        uint32_t b0, uint32_t b1) {
    asm volatile(
        "mma.sync.aligned.m16n8k16.row.col.f32.f16.f16.f32 "
        "{%0,%1,%2,%3}, {%4,%5,%6,%7}, {%8,%9}, {%0,%1,%2,%3};"
        : "+f"(c[0]), "+f"(c[1]), "+f"(c[2]), "+f"(c[3])
        : "r"(a[0]), "r"(a[1]), "r"(a[2]), "r"(a[3]), "r"(b0), "r"(b1));
}

#define MBAR_INIT(addr, cnt) \
    asm volatile("mbarrier.init.shared.b64 [%0], %1;" :: "r"(addr), "r"(cnt) : "memory")

#define MBAR_EXPECT_TX(addr, bytes) \
    asm volatile("mbarrier.arrive.expect_tx.shared.b64 _, [%0], %1;" \
                 :: "r"(addr), "r"(bytes) : "memory")

#define MBAR_WAIT(addr, ph) do {                                                  \
    uint32_t _d = 0;                                                              \
    do {                                                                          \
        asm volatile("{\n\t.reg .pred P;\n\t"                                     \
            "mbarrier.try_wait.parity.acquire.cta.shared::cta.b64 P, [%1], %2, 0x989680;\n\t" \
            "selp.b32 %0, 1, 0, P;\n\t}"                                          \
            : "=r"(_d) : "r"(addr), "r"(ph) : "memory");                          \
    } while (!_d);                                                                \
} while (0)

#define TMA_LOAD_2D(smem_addr, tmap, cx, cy, mbar) \
    asm volatile( \
        "cp.async.bulk.tensor.2d.shared::cta.global.tile.mbarrier::complete_tx::bytes " \
        "[%0], [%1, {%2, %3}], [%4];" \
        :: "r"(smem_addr), "l"(tmap), "r"(cx), "r"(cy), "r"(mbar) : "memory")

__device__ __forceinline__ uint32_t h2_bits(__half2 h) {
    return *reinterpret_cast<uint32_t*>(&h);
}

// ---------------------------------------------------------------------------
// Prep 1: convert x to fp16
// ---------------------------------------------------------------------------
__global__ __launch_bounds__(256) void convert_x_kernel(const float4* __restrict__ x,
                                                        uint2* __restrict__ xh, int n4) {
    int i = blockIdx.x * blockDim.x + threadIdx.x;
    int stride = gridDim.x * blockDim.x;
    for (; i < n4; i += stride) {
        float4 v = x[i];
        uint2 o;
        o.x = h2_bits(__floats2half2_rn(v.x, v.y));
        o.y = h2_bits(__floats2half2_rn(v.z, v.w));
        xh[i] = o;
    }
}

// ---------------------------------------------------------------------------
// Prep 2 (fused): per 128(o) x 64(i) tile:
//   phase 1: vectorized fills; L = B@A via fp16 HMMA (K=RANK=64, one shot)
//   phase 2: acc -> smem (reuse sB), coalesced dequant pass:
//            q as int4, L as 8B LDS, NF4*scale via lane-shuffle, wh as uint2
// ---------------------------------------------------------------------------
#define LROWH 72     // 64 + 8 pad halves = 144 B rows, conflict-free
__global__ __launch_bounds__(128) void lora_dequant_kernel(
    const float* __restrict__ lA, const float* __restrict__ lB,
    const int* __restrict__ q, const float* __restrict__ wscale,
    __half* __restrict__ wh) {
    __shared__ __half sB[128][LROWH];    // o x r  (mma A operand); reused as L tile
    __shared__ __half sAt[64][LROWH];    // i x r  (mma B operand)
    const int tid = threadIdx.x;
    const int o0 = blockIdx.y * 128;
    const int i0 = blockIdx.x * 64;

    // fill sB: lB rows are 64 consecutive floats -> float4 vector loads
#pragma unroll
    for (int it = 0; it < 16; it++) {
        const int idx = tid + it * 128;          // 0 .. 2047
        const int row = idx >> 4;                // 0..127
        const int c4 = idx & 15;                 // float4 chunk
        const float4 v = *reinterpret_cast<const float4*>(
            &lB[(size_t)(o0 + row) * RANK + c4 * 4]);
        *reinterpret_cast<__half2*>(&sB[row][c4 * 4]) = __floats2half2_rn(v.x, v.y);
        *reinterpret_cast<__half2*>(&sB[row][c4 * 4 + 2]) = __floats2half2_rn(v.z, v.w);
    }
    // fill sAt (transposed): load lA rows coalesced, scatter to columns
#pragma unroll
    for (int it = 0; it < 8; it++) {
        const int idx = tid + it * 128;          // 0 .. 1023
        const int r = idx >> 4;                  // 0..63
        const int c4 = idx & 15;
        const float4 v = *reinterpret_cast<const float4*>(
            &lA[(size_t)r * D_IN + i0 + c4 * 4]);
        sAt[c4 * 4 + 0][r] = __float2half(v.x);
        sAt[c4 * 4 + 1][r] = __float2half(v.y);
        sAt[c4 * 4 + 2][r] = __float2half(v.z);
        sAt[c4 * 4 + 3][r] = __float2half(v.w);
    }
    __syncthreads();

    const int warp = tid >> 5;
    const int lane = tid & 31;
    const int wm = (warp & 1) * 64;      // o offset
    const int wn = (warp >> 1) * 32;     // i offset

    const int lg = lane >> 3;
    const int lr = lane & 7;
    const int a_row = lr + (lg & 1) * 8;
    const int a_kof = (lg >> 1) * 8;
    const int b_row = lr + (lg >> 1) * 8;
    const int b_kof = (lg & 1) * 8;

    const uint32_t sb_base = (uint32_t)__cvta_generic_to_shared(&sB[0][0]);
    const uint32_t sa_base = (uint32_t)__cvta_generic_to_shared(&sAt[0][0]);

    float acc[4][4][4] = {};
#pragma unroll
    for (int kk = 0; kk < 4; kk++) {
        const int k0 = kk * 16;
        uint32_t af[4][4];
#pragma unroll
        for (int mi = 0; mi < 4; mi++) {
            uint32_t addr = sb_base + ((wm + mi * 16 + a_row) * LROWH + k0 + a_kof) * 2;
            LDMATRIX_X4(af[mi][0], af[mi][1], af[mi][2], af[mi][3], addr);
        }
        uint32_t bfr[2][4];
#pragma unroll
        for (int nj = 0; nj < 2; nj++) {
            uint32_t addr = sa_base + ((wn + nj * 16 + b_row) * LROWH + k0 + b_kof) * 2;
            LDMATRIX_X4(bfr[nj][0], bfr[nj][1], bfr[nj][2], bfr[nj][3], addr);
        }
#pragma unroll
        for (int mi = 0; mi < 4; mi++)
#pragma unroll
            for (int nj = 0; nj < 2; nj++) {
                mma_f16(acc[mi][nj * 2 + 0], af[mi], bfr[nj][0], bfr[nj][1]);
                mma_f16(acc[mi][nj * 2 + 1], af[mi], bfr[nj][2], bfr[nj][3]);
            }
    }

    // all warps done reading sB -> reuse it as the L tile
    __syncthreads();

    const int crow = lane >> 2;
    const int ccol = (lane & 3) * 2;
#pragma unroll
    for (int mi = 0; mi < 4; mi++) {
#pragma unroll
        for (int ni = 0; ni < 4; ni++) {
            const int row = wm + mi * 16 + crow;
            const int col = wn + ni * 8 + ccol;
            *reinterpret_cast<__half2*>(&sB[row][col]) =
                __floats2half2_rn(acc[mi][ni][0], acc[mi][ni][1]);
            *reinterpret_cast<__half2*>(&sB[row + 8][col]) =
                __floats2half2_rn(acc[mi][ni][2], acc[mi][ni][3]);
        }
    }
    __syncthreads();

    // coalesced dequant pass: 16 iters x 8 rows; half-warp covers one 64-col row
    const float nf4s = c_nf4[lane & 15] * wscale[0];   // premultiplied LUT
    const int drow = tid >> 4;             // 0..7
    const int dcol = (tid & 15) * 4;       // 0..60
#pragma unroll
    for (int g2 = 0; g2 < 16; g2++) {
        const int o_l = g2 * 8 + drow;
        const size_t o = (size_t)(o0 + o_l);
        const int4 qv = *reinterpret_cast<const int4*>(&q[o * D_IN + i0 + dcol]);
        const uint2 lv = *reinterpret_cast<const uint2*>(&sB[o_l][dcol]);
        const __half2 l0 = *reinterpret_cast<const __half2*>(&lv.x);
        const __half2 l1 = *reinterpret_cast<const __half2*>(&lv.y);
        const float f0 = __shfl_sync(0xffffffffu, nf4s, qv.x & 15) + 0.25f * __low2float(l0);
        const float f1 = __shfl_sync(0xffffffffu, nf4s, qv.y & 15) + 0.25f * __high2float(l0);
        const float f2 = __shfl_sync(0xffffffffu, nf4s, qv.z & 15) + 0.25f * __low2float(l1);
        const float f3 = __shfl_sync(0xffffffffu, nf4s, qv.w & 15) + 0.25f * __high2float(l1);
        uint2 ov;
        ov.x = h2_bits(__floats2half2_rn(f0, f1));
        ov.y = h2_bits(__floats2half2_rn(f2, f3));
        *reinterpret_cast<uint2*>(&wh[o * D_IN + i0 + dcol]) = ov;
    }
}

// ---------------------------------------------------------------------------
// Main GEMM: C[m,n] = sum_k Xh[m,k] * Wh[n,k]   (unchanged — at issue roofline)
// ---------------------------------------------------------------------------
__global__ void __launch_bounds__(128, 2)
gemm_f16_kernel(const __grid_constant__ CUtensorMap tma_a,
                const __grid_constant__ CUtensorMap tma_b,
                float* __restrict__ C) {
    extern __shared__ char smem[];
    const uint32_t sb = (uint32_t)__cvta_generic_to_shared(smem);

    const int tid = threadIdx.x;
    const int warp = tid >> 5;
    const int lane = tid & 31;

    const int bid = blockIdx.x;
    const int GROUP_M = 8;
    const int per_group = GROUP_M * N_TILES;
    const int g = bid / per_group, rem = bid % per_group;
    const int mt = g * GROUP_M + (rem % GROUP_M);
    const int nt = rem / GROUP_M;
    const int m0 = mt * TM, n0 = nt * TN;

    const int wm = (warp & 1) * 64;
    const int wn = (warp >> 1) * 64;

    if (tid == 0) {
        for (int s = 0; s < STAGES; s++)
            MBAR_INIT(sb + SMEM_FULL(s), 1);
        asm volatile("fence.proxy.async.shared::cta;" ::: "memory");
    }
    __syncthreads();

    if (tid == 0) {
#pragma unroll
        for (int s = 0; s < STAGES; s++) {
            MBAR_EXPECT_TX(sb + SMEM_FULL(s), A_STAGE_B + B_STAGE_B);
            TMA_LOAD_2D(sb + SMEM_A_OFF + s * A_STAGE_B, &tma_a, s * TK, m0,
                        sb + SMEM_FULL(s));
            TMA_LOAD_2D(sb + SMEM_B_OFF + s * B_STAGE_B, &tma_b, s * TK, n0,
                        sb + SMEM_FULL(s));
        }
    }

    float acc[4][8][4];
#pragma unroll
    for (int mi = 0; mi < 4; mi++)
#pragma unroll
        for (int ni = 0; ni < 8; ni++)
#pragma unroll
            for (int c = 0; c < 4; c++) acc[mi][ni][c] = 0.f;

    const int lg = lane >> 3;
    const int lr = lane & 7;
    const int a_row = lr + (lg & 1) * 8;
    const int a_kch = lg >> 1;
    const int b_row = lr + (lg >> 1) * 8;
    const int b_kch = lg & 1;

    uint32_t af[2][4][4];
    uint32_t bf[2][4][4];

    auto load_frag = [&](int buf, uint32_t a_st, uint32_t b_st, int kk) {
#pragma unroll
        for (int mi = 0; mi < 4; mi++) {
            const int row = wm + mi * 16 + a_row;
            const int ch = (2 * kk + a_kch) ^ (row & 7);
            uint32_t addr = a_st + row * 128 + ch * 16;
            LDMATRIX_X4(af[buf][mi][0], af[buf][mi][1], af[buf][mi][2], af[buf][mi][3], addr);
        }
#pragma unroll
        for (int nj = 0; nj < 4; nj++) {
            const int row = wn + nj * 16 + b_row;
            const int ch = (2 * kk + b_kch) ^ (row & 7);
            uint32_t addr = b_st + row * 128 + ch * 16;
            LDMATRIX_X4(bf[buf][nj][0], bf[buf][nj][1], bf[buf][nj][2], bf[buf][nj][3], addr);
        }
    };

    int cs = 0, cph = 0;

    MBAR_WAIT(sb + SMEM_FULL(0), 0);
    load_frag(0, sb + SMEM_A_OFF, sb + SMEM_B_OFF, 0);

    for (int kt = 0; kt < K_ITERS; kt++) {
        const uint32_t a_st = sb + SMEM_A_OFF + cs * A_STAGE_B;
        const uint32_t b_st = sb + SMEM_B_OFF + cs * B_STAGE_B;

        const int ncs = (cs + 1 == STAGES) ? 0 : cs + 1;
        const int nph = (cs + 1 == STAGES) ? (cph ^ 1) : cph;

#pragma unroll
        for (int kk = 0; kk < 4; kk++) {
            const int cur = kk & 1;
            if (kk < 3) {
                load_frag(cur ^ 1, a_st, b_st, kk + 1);
            } else if (kt + 1 < K_ITERS) {
                MBAR_WAIT(sb + SMEM_FULL(ncs), nph);
                load_frag(cur ^ 1, sb + SMEM_A_OFF + ncs * A_STAGE_B,
                          sb + SMEM_B_OFF + ncs * B_STAGE_B, 0);
            }
#pragma unroll
            for (int mi = 0; mi < 4; mi++)
#pragma unroll
                for (int nj = 0; nj < 4; nj++) {
                    mma_f16(acc[mi][nj * 2 + 0], af[cur][mi], bf[cur][nj][0], bf[cur][nj][1]);
                    mma_f16(acc[mi][nj * 2 + 1], af[cur][mi], bf[cur][nj][2], bf[cur][nj][3]);
                }
        }

        __syncthreads();

        if (tid == 0 && kt + STAGES < K_ITERS) {
            const int li = kt + STAGES;
            MBAR_EXPECT_TX(sb + SMEM_FULL(cs), A_STAGE_B + B_STAGE_B);
            TMA_LOAD_2D(sb + SMEM_A_OFF + cs * A_STAGE_B, &tma_a, li * TK, m0,
                        sb + SMEM_FULL(cs));
            TMA_LOAD_2D(sb + SMEM_B_OFF + cs * B_STAGE_B, &tma_b, li * TK, n0,
                        sb + SMEM_FULL(cs));
        }

        cs = ncs; cph = nph;
    }

    const int crow = lane >> 2;
    const int ccol = (lane & 3) * 2;
#pragma unroll
    for (int mi = 0; mi < 4; mi++) {
#pragma unroll
        for (int ni = 0; ni < 8; ni++) {
            const size_t m = (size_t)m0 + wm + mi * 16 + crow;
            const int n = n0 + wn + ni * 8 + ccol;
            float2 v0 = {acc[mi][ni][0], acc[mi][ni][1]};
            float2 v1 = {acc[mi][ni][2], acc[mi][ni][3]};
            *reinterpret_cast<float2*>(C + m * D_OUT + n) = v0;
            *reinterpret_cast<float2*>(C + (m + 8) * D_OUT + n) = v1;
        }
    }
}

// ---------------------------------------------------------------------------
// Host side
// ---------------------------------------------------------------------------
typedef CUresult (*EncodeFn)(CUtensorMap*, CUtensorMapDataType, cuuint32_t, void*,
                             const cuuint64_t*, const cuuint64_t*, const cuuint32_t*,
                             const cuuint32_t*, CUtensorMapInterleave, CUtensorMapSwizzle,
                             CUtensorMapL2promotion, CUtensorMapFloatOOBfill);

static EncodeFn get_encode_fn() {
    void* fn = nullptr;
    cudaDriverEntryPointQueryResult st;
#if CUDART_VERSION >= 12050
    cudaGetDriverEntryPointByVersion("cuTensorMapEncodeTiled", &fn, 12000,
                                     cudaEnableDefault, &st);
#else
    cudaGetDriverEntryPoint("cuTensorMapEncodeTiled", &fn, cudaEnableDefault, &st);
#endif
    return (EncodeFn)fn;
}

static void encode_2d_f16(EncodeFn fn, CUtensorMap* tm, void* ptr,
                          uint64_t dim0, uint64_t dim1, uint32_t box0, uint32_t box1) {
    cuuint64_t dims[2] = {dim0, dim1};
    cuuint64_t strides[1] = {dim0 * 2};
    cuuint32_t box[2] = {box0, box1};
    cuuint32_t es[2] = {1, 1};
    fn(tm, CU_TENSOR_MAP_DATA_TYPE_FLOAT16, 2, ptr, dims, strides, box, es,
       CU_TENSOR_MAP_INTERLEAVE_NONE, CU_TENSOR_MAP_SWIZZLE_128B,
       CU_TENSOR_MAP_L2_PROMOTION_L2_128B, CU_TENSOR_MAP_FLOAT_OOB_FILL_NONE);
}

extern "C" void kernel_launch(void* const* d_in, const int* in_sizes, int n_in,
                              void* d_out, int out_size) {
    const float* x  = (const float*)d_in[0];
    const int*   q  = (const int*)d_in[1];
    const float* ws = (const float*)d_in[2];
    const float* lA = (const float*)d_in[3];
    const float* lB = (const float*)d_in[4];
    float* out = (float*)d_out;

    __half* wh = nullptr;
    __half* xh = nullptr;
    cudaGetSymbolAddress((void**)&wh, g_wh);
    cudaGetSymbolAddress((void**)&xh, g_xh);

    convert_x_kernel<<<2048, 256>>>((const float4*)x, (uint2*)xh,
                                    (int)((size_t)M_TOT * D_IN / 4));
    dim3 lgrid(D_IN / 64, D_OUT / 128);
    lora_dequant_kernel<<<lgrid, 128>>>(lA, lB, q, ws, wh);

    EncodeFn enc = get_encode_fn();
    CUtensorMap tm_a, tm_b;
    encode_2d_f16(enc, &tm_a, xh, D_IN, M_TOT, TK, TM);
    encode_2d_f16(enc, &tm_b, wh, D_IN, D_OUT, TK, TN);

    cudaFuncSetAttribute(gemm_f16_kernel,
                         cudaFuncAttributeMaxDynamicSharedMemorySize, SMEM_BYTES);
    gemm_f16_kernel<<<M_TILES * N_TILES, 128, SMEM_BYTES>>>(tm_a, tm_b, out);
}

// round 17
// speedup vs baseline: 1.2162x; 1.0001x over previous
#include <cuda_runtime.h>
#include <cuda.h>
#include <cuda_fp16.h>
#include <cstdint>

// ---------------------------------------------------------------------------
// Problem constants
// ---------------------------------------------------------------------------
#define D_IN   4096
#define D_OUT  4096
#define M_TOT  8192
#define RANK   64

// GEMM tiling (fp16 operands, fp32 accumulate)
#define TM 128
#define TN 128
#define TK 64                        // halves per K-stage = 128 B (one SW128 row)
#define STAGES 3
#define K_ITERS (D_IN / TK)          // 64
#define M_TILES (M_TOT / TM)         // 64
#define N_TILES (D_OUT / TN)         // 32

#define A_STAGE_B (TM * 128)         // 16384 bytes
#define B_STAGE_B (TN * 128)         // 16384 bytes
#define SMEM_FULL(s)  ((s) * 8)
#define SMEM_A_OFF    1024
#define SMEM_B_OFF    (SMEM_A_OFF + STAGES * A_STAGE_B)     // 50176
#define SMEM_BYTES    (SMEM_B_OFF + STAGES * B_STAGE_B)     // 99328 -> 2 CTAs/SM

// ---------------------------------------------------------------------------
// Device globals (allocation-free scratch)
// ---------------------------------------------------------------------------
__constant__ float c_nf4[16] = {
    -1.0f, -0.6962f, -0.5251f, -0.3949f, -0.2844f, -0.1848f,
    -0.0911f, 0.0f, 0.0796f, 0.1609f, 0.2461f, 0.3379f,
    0.4407f, 0.5626f, 0.723f, 1.0f};

__device__ __align__(1024) __half g_wh[(size_t)D_OUT * D_IN];  // W_eff fp16
__device__ __align__(1024) __half g_xh[(size_t)M_TOT * D_IN];  // x fp16

// ---------------------------------------------------------------------------
// PTX helpers
// ---------------------------------------------------------------------------
#define LDMATRIX_X4(r0, r1, r2, r3, addr)                                     \
    asm volatile("ldmatrix.sync.aligned.m8n8.x4.shared.b16 {%0,%1,%2,%3}, [%4];" \
                 : "=r"(r0), "=r"(r1), "=r"(r2), "=r"(r3) : "r"(addr))

__device__ __forceinline__ void mma_f16(float* c, const uint32_t* a,
                                        uint32_t b0, uint32_t b1) {
    asm volatile(
        "mma.sync.aligned.m16n8k16.row.col.f32.f16.f16.f32 "
        "{%0,%1,%2,%3}, {%4,%5,%6,%7}, {%8,%9}, {%0,%1,%2,%3};"
        : "+f"(c[0]), "+f"(c[1]), "+f"(c[2]), "+f"(c[3])
        : "r"(a[0]), "r"(a[1]), "r"(a[2]), "r"(a[3]), "r"(b0), "r"(b1));
}

#define MBAR_INIT(addr, cnt) \
    asm volatile("mbarrier.init.shared.b64 [%0], %1;" :: "r"(addr), "r"(cnt) : "memory")

#define MBAR_EXPECT_TX(addr, bytes) \
    asm volatile("mbarrier.arrive.expect_tx.shared.b64 _, [%0], %1;" \
                 :: "r"(addr), "r"(bytes) : "memory")

#define MBAR_WAIT(addr, ph) do {                                                  \
    uint32_t _d = 0;                                                              \
    do {                                                                          \
        asm volatile("{\n\t.reg .pred P;\n\t"                                     \
            "mbarrier.try_wait.parity.acquire.cta.shared::cta.b64 P, [%1], %2, 0x989680;\n\t" \
            "selp.b32 %0, 1, 0, P;\n\t}"                                          \
            : "=r"(_d) : "r"(addr), "r"(ph) : "memory");                          \
    } while (!_d);                                                                \
} while (0)

#define TMA_LOAD_2D(smem_addr, tmap, cx, cy, mbar) \
    asm volatile( \
        "cp.async.bulk.tensor.2d.shared::cta.global.tile.mbarrier::complete_tx::bytes " \
        "[%0], [%1, {%2, %3}], [%4];" \
        :: "r"(smem_addr), "l"(tmap), "r"(cx), "r"(cy), "r"(mbar) : "memory")

__device__ __forceinline__ uint32_t h2_bits(__half2 h) {
    return *reinterpret_cast<uint32_t*>(&h);
}

// ---------------------------------------------------------------------------
// Prep 1: convert x to fp16
// ---------------------------------------------------------------------------
__global__ __launch_bounds__(256) void convert_x_kernel(const float4* __restrict__ x,
                                                        uint2* __restrict__ xh, int n4) {
    int i = blockIdx.x * blockDim.x + threadIdx.x;
    int stride = gridDim.x * blockDim.x;
    for (; i < n4; i += stride) {
        float4 v = x[i];
        uint2 o;
        o.x = h2_bits(__floats2half2_rn(v.x, v.y));
        o.y = h2_bits(__floats2half2_rn(v.z, v.w));
        xh[i] = o;
    }
}

// ---------------------------------------------------------------------------
// Prep 2 (fused): per 128(o) x 64(i) tile:
//   phase 1: vectorized fills; L = B@A via fp16 HMMA (K=RANK=64, one shot)
//   phase 2: acc -> smem (reuse sB), coalesced dequant pass
// ---------------------------------------------------------------------------
#define LROWH 72     // 64 + 8 pad halves = 144 B rows, conflict-free
__global__ __launch_bounds__(128) void lora_dequant_kernel(
    const float* __restrict__ lA, const float* __restrict__ lB,
    const int* __restrict__ q, const float* __restrict__ wscale,
    __half* __restrict__ wh) {
    __shared__ __half sB[128][LROWH];    // o x r  (mma A operand); reused as L tile
    __shared__ __half sAt[64][LROWH];    // i x r  (mma B operand)
    const int tid = threadIdx.x;
    const int o0 = blockIdx.y * 128;
    const int i0 = blockIdx.x * 64;

    // fill sB: lB rows are 64 consecutive floats -> float4 vector loads
#pragma unroll
    for (int it = 0; it < 16; it++) {
        const int idx = tid + it * 128;          // 0 .. 2047
        const int row = idx >> 4;                // 0..127
        const int c4 = idx & 15;                 // float4 chunk
        const float4 v = *reinterpret_cast<const float4*>(
            &lB[(size_t)(o0 + row) * RANK + c4 * 4]);
        *reinterpret_cast<__half2*>(&sB[row][c4 * 4]) = __floats2half2_rn(v.x, v.y);
        *reinterpret_cast<__half2*>(&sB[row][c4 * 4 + 2]) = __floats2half2_rn(v.z, v.w);
    }
    // fill sAt (transposed): load lA rows coalesced, scatter to columns
#pragma unroll
    for (int it = 0; it < 8; it++) {
        const int idx = tid + it * 128;          // 0 .. 1023
        const int r = idx >> 4;                  // 0..63
        const int c4 = idx & 15;
        const float4 v = *reinterpret_cast<const float4*>(
            &lA[(size_t)r * D_IN + i0 + c4 * 4]);
        sAt[c4 * 4 + 0][r] = __float2half(v.x);
        sAt[c4 * 4 + 1][r] = __float2half(v.y);
        sAt[c4 * 4 + 2][r] = __float2half(v.z);
        sAt[c4 * 4 + 3][r] = __float2half(v.w);
    }
    __syncthreads();

    const int warp = tid >> 5;
    const int lane = tid & 31;
    const int wm = (warp & 1) * 64;      // o offset
    const int wn = (warp >> 1) * 32;     // i offset

    const int lg = lane >> 3;
    const int lr = lane & 7;
    const int a_row = lr + (lg & 1) * 8;
    const int a_kof = (lg >> 1) * 8;
    const int b_row = lr + (lg >> 1) * 8;
    const int b_kof = (lg & 1) * 8;

    const uint32_t sb_base = (uint32_t)__cvta_generic_to_shared(&sB[0][0]);
    const uint32_t sa_base = (uint32_t)__cvta_generic_to_shared(&sAt[0][0]);

    float acc[4][4][4] = {};
#pragma unroll
    for (int kk = 0; kk < 4; kk++) {
        const int k0 = kk * 16;
        uint32_t af[4][4];
#pragma unroll
        for (int mi = 0; mi < 4; mi++) {
            uint32_t addr = sb_base + ((wm + mi * 16 + a_row) * LROWH + k0 + a_kof) * 2;
            LDMATRIX_X4(af[mi][0], af[mi][1], af[mi][2], af[mi][3], addr);
        }
        uint32_t bfr[2][4];
#pragma unroll
        for (int nj = 0; nj < 2; nj++) {
            uint32_t addr = sa_base + ((wn + nj * 16 + b_row) * LROWH + k0 + b_kof) * 2;
            LDMATRIX_X4(bfr[nj][0], bfr[nj][1], bfr[nj][2], bfr[nj][3], addr);
        }
#pragma unroll
        for (int mi = 0; mi < 4; mi++)
#pragma unroll
            for (int nj = 0; nj < 2; nj++) {
                mma_f16(acc[mi][nj * 2 + 0], af[mi], bfr[nj][0], bfr[nj][1]);
                mma_f16(acc[mi][nj * 2 + 1], af[mi], bfr[nj][2], bfr[nj][3]);
            }
    }

    // all warps done reading sB -> reuse it as the L tile
    __syncthreads();

    const int crow = lane >> 2;
    const int ccol = (lane & 3) * 2;
#pragma unroll
    for (int mi = 0; mi < 4; mi++) {
#pragma unroll
        for (int ni = 0; ni < 4; ni++) {
            const int row = wm + mi * 16 + crow;
            const int col = wn + ni * 8 + ccol;
            *reinterpret_cast<__half2*>(&sB[row][col]) =
                __floats2half2_rn(acc[mi][ni][0], acc[mi][ni][1]);
            *reinterpret_cast<__half2*>(&sB[row + 8][col]) =
                __floats2half2_rn(acc[mi][ni][2], acc[mi][ni][3]);
        }
    }
    __syncthreads();

    // coalesced dequant pass: 16 iters x 8 rows; half-warp covers one 64-col row
    const float nf4s = c_nf4[lane & 15] * wscale[0];   // premultiplied LUT
    const int drow = tid >> 4;             // 0..7
    const int dcol = (tid & 15) * 4;       // 0..60
#pragma unroll
    for (int g2 = 0; g2 < 16; g2++) {
        const int o_l = g2 * 8 + drow;
        const size_t o = (size_t)(o0 + o_l);
        const int4 qv = *reinterpret_cast<const int4*>(&q[o * D_IN + i0 + dcol]);
        const uint2 lv = *reinterpret_cast<const uint2*>(&sB[o_l][dcol]);
        const __half2 l0 = *reinterpret_cast<const __half2*>(&lv.x);
        const __half2 l1 = *reinterpret_cast<const __half2*>(&lv.y);
        const float f0 = __shfl_sync(0xffffffffu, nf4s, qv.x & 15) + 0.25f * __low2float(l0);
        const float f1 = __shfl_sync(0xffffffffu, nf4s, qv.y & 15) + 0.25f * __high2float(l0);
        const float f2 = __shfl_sync(0xffffffffu, nf4s, qv.z & 15) + 0.25f * __low2float(l1);
        const float f3 = __shfl_sync(0xffffffffu, nf4s, qv.w & 15) + 0.25f * __high2float(l1);
        uint2 ov;
        ov.x = h2_bits(__floats2half2_rn(f0, f1));
        ov.y = h2_bits(__floats2half2_rn(f2, f3));
        *reinterpret_cast<uint2*>(&wh[o * D_IN + i0 + dcol]) = ov;
    }
}

// ---------------------------------------------------------------------------
// Main GEMM: C[m,n] = sum_k Xh[m,k] * Wh[n,k]   (unchanged — at issue roofline)
// ---------------------------------------------------------------------------
__global__ void __launch_bounds__(128, 2)
gemm_f16_kernel(const __grid_constant__ CUtensorMap tma_a,
                const __grid_constant__ CUtensorMap tma_b,
                float* __restrict__ C) {
    extern __shared__ char smem[];
    const uint32_t sb = (uint32_t)__cvta_generic_to_shared(smem);

    const int tid = threadIdx.x;
    const int warp = tid >> 5;
    const int lane = tid & 31;

    const int bid = blockIdx.x;
    const int GROUP_M = 8;
    const int per_group = GROUP_M * N_TILES;
    const int g = bid / per_group, rem = bid % per_group;
    const int mt = g * GROUP_M + (rem % GROUP_M);
    const int nt = rem / GROUP_M;
    const int m0 = mt * TM, n0 = nt * TN;

    const int wm = (warp & 1) * 64;
    const int wn = (warp >> 1) * 64;

    if (tid == 0) {
        for (int s = 0; s < STAGES; s++)
            MBAR_INIT(sb + SMEM_FULL(s), 1);
        asm volatile("fence.proxy.async.shared::cta;" ::: "memory");
    }
    __syncthreads();

    if (tid == 0) {
#pragma unroll
        for (int s = 0; s < STAGES; s++) {
            MBAR_EXPECT_TX(sb + SMEM_FULL(s), A_STAGE_B + B_STAGE_B);
            TMA_LOAD_2D(sb + SMEM_A_OFF + s * A_STAGE_B, &tma_a, s * TK, m0,
                        sb + SMEM_FULL(s));
            TMA_LOAD_2D(sb + SMEM_B_OFF + s * B_STAGE_B, &tma_b, s * TK, n0,
                        sb + SMEM_FULL(s));
        }
    }

    float acc[4][8][4];
#pragma unroll
    for (int mi = 0; mi < 4; mi++)
#pragma unroll
        for (int ni = 0; ni < 8; ni++)
#pragma unroll
            for (int c = 0; c < 4; c++) acc[mi][ni][c] = 0.f;

    const int lg = lane >> 3;
    const int lr = lane & 7;
    const int a_row = lr + (lg & 1) * 8;
    const int a_kch = lg >> 1;
    const int b_row = lr + (lg >> 1) * 8;
    const int b_kch = lg & 1;

    uint32_t af[2][4][4];
    uint32_t bf[2][4][4];

    auto load_frag = [&](int buf, uint32_t a_st, uint32_t b_st, int kk) {
#pragma unroll
        for (int mi = 0; mi < 4; mi++) {
            const int row = wm + mi * 16 + a_row;
            const int ch = (2 * kk + a_kch) ^ (row & 7);
            uint32_t addr = a_st + row * 128 + ch * 16;
            LDMATRIX_X4(af[buf][mi][0], af[buf][mi][1], af[buf][mi][2], af[buf][mi][3], addr);
        }
#pragma unroll
        for (int nj = 0; nj < 4; nj++) {
            const int row = wn + nj * 16 + b_row;
            const int ch = (2 * kk + b_kch) ^ (row & 7);
            uint32_t addr = b_st + row * 128 + ch * 16;
            LDMATRIX_X4(bf[buf][nj][0], bf[buf][nj][1], bf[buf][nj][2], bf[buf][nj][3], addr);
        }
    };

    int cs = 0, cph = 0;

    MBAR_WAIT(sb + SMEM_FULL(0), 0);
    load_frag(0, sb + SMEM_A_OFF, sb + SMEM_B_OFF, 0);

    for (int kt = 0; kt < K_ITERS; kt++) {
        const uint32_t a_st = sb + SMEM_A_OFF + cs * A_STAGE_B;
        const uint32_t b_st = sb + SMEM_B_OFF + cs * B_STAGE_B;

        const int ncs = (cs + 1 == STAGES) ? 0 : cs + 1;
        const int nph = (cs + 1 == STAGES) ? (cph ^ 1) : cph;

#pragma unroll
        for (int kk = 0; kk < 4; kk++) {
            const int cur = kk & 1;
            if (kk < 3) {
                load_frag(cur ^ 1, a_st, b_st, kk + 1);
            } else if (kt + 1 < K_ITERS) {
                MBAR_WAIT(sb + SMEM_FULL(ncs), nph);
                load_frag(cur ^ 1, sb + SMEM_A_OFF + ncs * A_STAGE_B,
                          sb + SMEM_B_OFF + ncs * B_STAGE_B, 0);
            }
#pragma unroll
            for (int mi = 0; mi < 4; mi++)
#pragma unroll
                for (int nj = 0; nj < 4; nj++) {
                    mma_f16(acc[mi][nj * 2 + 0], af[cur][mi], bf[cur][nj][0], bf[cur][nj][1]);
                    mma_f16(acc[mi][nj * 2 + 1], af[cur][mi], bf[cur][nj][2], bf[cur][nj][3]);
                }
        }

        __syncthreads();

        if (tid == 0 && kt + STAGES < K_ITERS) {
            const int li = kt + STAGES;
            MBAR_EXPECT_TX(sb + SMEM_FULL(cs), A_STAGE_B + B_STAGE_B);
            TMA_LOAD_2D(sb + SMEM_A_OFF + cs * A_STAGE_B, &tma_a, li * TK, m0,
                        sb + SMEM_FULL(cs));
            TMA_LOAD_2D(sb + SMEM_B_OFF + cs * B_STAGE_B, &tma_b, li * TK, n0,
                        sb + SMEM_FULL(cs));
        }

        cs = ncs; cph = nph;
    }

    const int crow = lane >> 2;
    const int ccol = (lane & 3) * 2;
#pragma unroll
    for (int mi = 0; mi < 4; mi++) {
#pragma unroll
        for (int ni = 0; ni < 8; ni++) {
            const size_t m = (size_t)m0 + wm + mi * 16 + crow;
            const int n = n0 + wn + ni * 8 + ccol;
            float2 v0 = {acc[mi][ni][0], acc[mi][ni][1]};
            float2 v1 = {acc[mi][ni][2], acc[mi][ni][3]};
            *reinterpret_cast<float2*>(C + m * D_OUT + n) = v0;
            *reinterpret_cast<float2*>(C + (m + 8) * D_OUT + n) = v1;
        }
    }
}

// ---------------------------------------------------------------------------
// Host side
// ---------------------------------------------------------------------------
typedef CUresult (*EncodeFn)(CUtensorMap*, CUtensorMapDataType, cuuint32_t, void*,
                             const cuuint64_t*, const cuuint64_t*, const cuuint32_t*,
                             const cuuint32_t*, CUtensorMapInterleave, CUtensorMapSwizzle,
                             CUtensorMapL2promotion, CUtensorMapFloatOOBfill);

static EncodeFn get_encode_fn() {
    void* fn = nullptr;
    cudaDriverEntryPointQueryResult st;
#if CUDART_VERSION >= 12050
    cudaGetDriverEntryPointByVersion("cuTensorMapEncodeTiled", &fn, 12000,
                                     cudaEnableDefault, &st);
#else
    cudaGetDriverEntryPoint("cuTensorMapEncodeTiled", &fn, cudaEnableDefault, &st);
#endif
    return (EncodeFn)fn;
}

static void encode_2d_f16(EncodeFn fn, CUtensorMap* tm, void* ptr,
                          uint64_t dim0, uint64_t dim1, uint32_t box0, uint32_t box1) {
    cuuint64_t dims[2] = {dim0, dim1};
    cuuint64_t strides[1] = {dim0 * 2};
    cuuint32_t box[2] = {box0, box1};
    cuuint32_t es[2] = {1, 1};
    fn(tm, CU_TENSOR_MAP_DATA_TYPE_FLOAT16, 2, ptr, dims, strides, box, es,
       CU_TENSOR_MAP_INTERLEAVE_NONE, CU_TENSOR_MAP_SWIZZLE_128B,
       CU_TENSOR_MAP_L2_PROMOTION_L2_128B, CU_TENSOR_MAP_FLOAT_OOB_FILL_NONE);
}

extern "C" void kernel_launch(void* const* d_in, const int* in_sizes, int n_in,
                              void* d_out, int out_size) {
    const float* x  = (const float*)d_in[0];
    const int*   q  = (const int*)d_in[1];
    const float* ws = (const float*)d_in[2];
    const float* lA = (const float*)d_in[3];
    const float* lB = (const float*)d_in[4];
    float* out = (float*)d_out;

    __half* wh = nullptr;
    __half* xh = nullptr;
    cudaGetSymbolAddress((void**)&wh, g_wh);
    cudaGetSymbolAddress((void**)&xh, g_xh);

    // One-time host resources (created on the uncaptured correctness call;
    // only record/wait — both graph-capturable — happen during capture).
    static cudaStream_t s2 = nullptr;
    static cudaEvent_t ev_fork = nullptr, ev_join = nullptr;
    if (s2 == nullptr) {
        cudaStreamCreateWithFlags(&s2, cudaStreamNonBlocking);
        cudaEventCreateWithFlags(&ev_fork, cudaEventDisableTiming);
        cudaEventCreateWithFlags(&ev_join, cudaEventDisableTiming);
    }

    // fork: prep kernels are independent (disjoint in/out) -> run concurrently
    cudaEventRecord(ev_fork, 0);
    cudaStreamWaitEvent(s2, ev_fork, 0);

    convert_x_kernel<<<2048, 256>>>((const float4*)x, (uint2*)xh,
                                    (int)((size_t)M_TOT * D_IN / 4));
    dim3 lgrid(D_IN / 64, D_OUT / 128);
    lora_dequant_kernel<<<lgrid, 128, 0, s2>>>(lA, lB, q, ws, wh);

    // join: GEMM depends on both xh and wh
    cudaEventRecord(ev_join, s2);
    cudaStreamWaitEvent(0, ev_join, 0);

    EncodeFn enc = get_encode_fn();
    CUtensorMap tm_a, tm_b;
    encode_2d_f16(enc, &tm_a, xh, D_IN, M_TOT, TK, TM);
    encode_2d_f16(enc, &tm_b, wh, D_IN, D_OUT, TK, TN);

    cudaFuncSetAttribute(gemm_f16_kernel,
                         cudaFuncAttributeMaxDynamicSharedMemorySize, SMEM_BYTES);
    gemm_f16_kernel<<<M_TILES * N_TILES, 128, SMEM_BYTES>>>(tm_a, tm_b, out);
}